// round 1
// baseline (speedup 1.0000x reference)
#include <cuda_runtime.h>
#include <cuda_bf16.h>
#include <cstdint>

// Problem constants (fixed shapes for this dataset)
#define NMAX 100000
#define EMAX 1600000
#define IN_F 256
#define HID 128
#define OUT_F 64

// Scratch (bss, no runtime allocation)
__device__ float g_deg[NMAX];
__device__ float g_dinv[NMAX];
__device__ float g_h1[(size_t)NMAX * HID];     // x @ W1
__device__ float g_agg1[(size_t)NMAX * HID];   // aggregated layer-1
__device__ float g_h2[(size_t)NMAX * OUT_F];   // relu(agg1+b1) @ W2

// ---------------------------------------------------------------------------
// degree / normalization
// ---------------------------------------------------------------------------
__global__ void k_deg_init(float* deg, int n) {
    int i = blockIdx.x * blockDim.x + threadIdx.x;
    if (i < n) deg[i] = 1.0f;  // self loop
}

__global__ void k_deg_count(const int* __restrict__ dst, float* deg, int e) {
    int i = blockIdx.x * blockDim.x + threadIdx.x;
    if (i < e) atomicAdd(&deg[dst[i]], 1.0f);
}

__global__ void k_dinv(const float* __restrict__ deg, float* dinv, int n) {
    int i = blockIdx.x * blockDim.x + threadIdx.x;
    if (i < n) dinv[i] = rsqrtf(deg[i]);  // deg >= 1 always
}

// ---------------------------------------------------------------------------
// Generic register-blocked SGEMM: C[M,N] = op(A)[M,K] @ B[K,N]
// FUSE_RELU_BIAS: A element a -> relu(a + biasA[k])   (bias indexed by K dim)
// ---------------------------------------------------------------------------
template <int BM, int BN, int BK, int TM, int TN, bool FUSE_RELU_BIAS>
__global__ void __launch_bounds__((BM / TM) * (BN / TN))
k_sgemm(int M, int N, int K,
        const float* __restrict__ A,
        const float* __restrict__ B,
        const float* __restrict__ biasA,
        float* __restrict__ C) {
    constexpr int THREADS = (BM / TM) * (BN / TN);
    __shared__ float As[BK][BM];
    __shared__ float Bs[BK][BN];

    const int block_row = blockIdx.x * BM;
    const int block_col = blockIdx.y * BN;
    const int tid = threadIdx.x;
    const int tcol = tid % (BN / TN);
    const int trow = tid / (BN / TN);

    float acc[TM][TN];
#pragma unroll
    for (int i = 0; i < TM; i++)
#pragma unroll
        for (int j = 0; j < TN; j++) acc[i][j] = 0.f;

    for (int k0 = 0; k0 < K; k0 += BK) {
        // --- load A tile (BM x BK), float4 along K, store transposed
#pragma unroll
        for (int i = tid * 4; i < BM * BK; i += THREADS * 4) {
            int m = i / BK;
            int kk = i % BK;
            int gr = block_row + m;
            float4 v = make_float4(0.f, 0.f, 0.f, 0.f);
            if (gr < M)
                v = *reinterpret_cast<const float4*>(A + (size_t)gr * K + k0 + kk);
            if (FUSE_RELU_BIAS) {
                v.x = fmaxf(v.x + biasA[k0 + kk + 0], 0.f);
                v.y = fmaxf(v.y + biasA[k0 + kk + 1], 0.f);
                v.z = fmaxf(v.z + biasA[k0 + kk + 2], 0.f);
                v.w = fmaxf(v.w + biasA[k0 + kk + 3], 0.f);
            }
            As[kk + 0][m] = v.x;
            As[kk + 1][m] = v.y;
            As[kk + 2][m] = v.z;
            As[kk + 3][m] = v.w;
        }
        // --- load B tile (BK x BN), float4 along N
#pragma unroll
        for (int i = tid * 4; i < BK * BN; i += THREADS * 4) {
            int kk = i / BN;
            int n = i % BN;
            float4 v = *reinterpret_cast<const float4*>(
                B + (size_t)(k0 + kk) * N + block_col + n);
            *reinterpret_cast<float4*>(&Bs[kk][n]) = v;
        }
        __syncthreads();

        float regM[TM], regN[TN];
#pragma unroll
        for (int k = 0; k < BK; k++) {
#pragma unroll
            for (int i = 0; i < TM; i++) regM[i] = As[k][trow * TM + i];
#pragma unroll
            for (int j = 0; j < TN; j++) regN[j] = Bs[k][tcol * TN + j];
#pragma unroll
            for (int i = 0; i < TM; i++)
#pragma unroll
                for (int j = 0; j < TN; j++)
                    acc[i][j] = fmaf(regM[i], regN[j], acc[i][j]);
        }
        __syncthreads();
    }

    // --- store
#pragma unroll
    for (int i = 0; i < TM; i++) {
        int gr = block_row + trow * TM + i;
        if (gr >= M) continue;
#pragma unroll
        for (int j = 0; j < TN; j += 4) {
            float4 v = make_float4(acc[i][j], acc[i][j + 1], acc[i][j + 2],
                                   acc[i][j + 3]);
            *reinterpret_cast<float4*>(C + (size_t)gr * N + block_col +
                                       tcol * TN + j) = v;
        }
    }
}

// ---------------------------------------------------------------------------
// Self-loop initialization of aggregation buffers
// ---------------------------------------------------------------------------
__global__ void k_self_init_hid(const float* __restrict__ h,
                                const float* __restrict__ dinv,
                                float* __restrict__ agg, int n) {
    int idx = blockIdx.x * blockDim.x + threadIdx.x;
    if (idx >= n * HID) return;
    int node = idx / HID;
    float di = dinv[node];
    agg[idx] = h[idx] * di * di;
}

__global__ void k_self_init_out(const float* __restrict__ h,
                                const float* __restrict__ dinv,
                                const float* __restrict__ b2,
                                float* __restrict__ out, int n) {
    int idx = blockIdx.x * blockDim.x + threadIdx.x;
    if (idx >= n * OUT_F) return;
    int node = idx / OUT_F;
    int f = idx % OUT_F;
    float di = dinv[node];
    out[idx] = h[idx] * di * di + b2[f];
}

// ---------------------------------------------------------------------------
// Warp-per-edge scatter-add:   agg[dst] += h[src] * dinv[src]*dinv[dst]
// ---------------------------------------------------------------------------
template <int F>
__global__ void k_edge_agg(const float* __restrict__ h,
                           float* __restrict__ agg,
                           const int* __restrict__ src,
                           const int* __restrict__ dst,
                           const float* __restrict__ dinv, int e) {
    int w = (blockIdx.x * blockDim.x + threadIdx.x) >> 5;
    int lane = threadIdx.x & 31;
    if (w >= e) return;
    int s = src[w];
    int d = dst[w];
    float c = dinv[s] * dinv[d];
    const float* hp = h + (size_t)s * F;
    float* ap = agg + (size_t)d * F;
    if (F == 128) {
        float4 v = *reinterpret_cast<const float4*>(hp + lane * 4);
        atomicAdd(ap + lane * 4 + 0, v.x * c);
        atomicAdd(ap + lane * 4 + 1, v.y * c);
        atomicAdd(ap + lane * 4 + 2, v.z * c);
        atomicAdd(ap + lane * 4 + 3, v.w * c);
    } else {  // F == 64
        float2 v = *reinterpret_cast<const float2*>(hp + lane * 2);
        atomicAdd(ap + lane * 2 + 0, v.x * c);
        atomicAdd(ap + lane * 2 + 1, v.y * c);
    }
}

// ---------------------------------------------------------------------------
// Launch
// ---------------------------------------------------------------------------
extern "C" void kernel_launch(void* const* d_in, const int* in_sizes, int n_in,
                              void* d_out, int out_size) {
    const float* x = (const float*)d_in[0];
    const int* ei = (const int*)d_in[1];
    const float* W1 = (const float*)d_in[2];
    const float* b1 = (const float*)d_in[3];
    const float* W2 = (const float*)d_in[4];
    const float* b2 = (const float*)d_in[5];
    float* out = (float*)d_out;

    const int n = in_sizes[0] / IN_F;  // 100000
    const int e = in_sizes[1] / 2;     // 1600000
    const int* src = ei;
    const int* dst = ei + e;

    float *p_deg, *p_dinv, *p_h1, *p_agg1, *p_h2;
    cudaGetSymbolAddress((void**)&p_deg, g_deg);
    cudaGetSymbolAddress((void**)&p_dinv, g_dinv);
    cudaGetSymbolAddress((void**)&p_h1, g_h1);
    cudaGetSymbolAddress((void**)&p_agg1, g_agg1);
    cudaGetSymbolAddress((void**)&p_h2, g_h2);

    // 1. degree + normalization
    k_deg_init<<<(n + 255) / 256, 256>>>(p_deg, n);
    k_deg_count<<<(e + 255) / 256, 256>>>(dst, p_deg, e);
    k_dinv<<<(n + 255) / 256, 256>>>(p_deg, p_dinv, n);

    // 2. GEMM1: h1 = x @ W1    [100000 x 256] @ [256 x 128]
    {
        constexpr int BM = 128, BN = 128, BK = 16, TM = 8, TN = 8;
        dim3 grid((n + BM - 1) / BM, (HID + BN - 1) / BN);
        k_sgemm<BM, BN, BK, TM, TN, false>
            <<<grid, (BM / TM) * (BN / TN)>>>(n, HID, IN_F, x, W1, nullptr, p_h1);
    }

    // 3. Layer-1 aggregation: self loops + edges
    k_self_init_hid<<<((size_t)n * HID + 255) / 256, 256>>>(p_h1, p_dinv, p_agg1, n);
    k_edge_agg<HID><<<(e + 7) / 8, 256>>>(p_h1, p_agg1, src, dst, p_dinv, e);

    // 4. GEMM2: h2 = relu(agg1 + b1) @ W2    [100000 x 128] @ [128 x 64]
    {
        constexpr int BM = 128, BN = 64, BK = 16, TM = 8, TN = 4;
        dim3 grid((n + BM - 1) / BM, (OUT_F + BN - 1) / BN);
        k_sgemm<BM, BN, BK, TM, TN, true>
            <<<grid, (BM / TM) * (BN / TN)>>>(n, OUT_F, HID, p_agg1, W2, b1, p_h2);
    }

    // 5. Layer-2 aggregation into d_out: self loops (+bias) + edges
    k_self_init_out<<<((size_t)n * OUT_F + 255) / 256, 256>>>(p_h2, p_dinv, b2, out, n);
    k_edge_agg<OUT_F><<<(e + 7) / 8, 256>>>(p_h2, out, src, dst, p_dinv, e);
}

// round 2
// speedup vs baseline: 2.4356x; 2.4356x over previous
#include <cuda_runtime.h>
#include <cuda_bf16.h>
#include <cstdint>

#define NMAX 100000
#define EMAX 1600000
#define IN_F 256
#define HID 128
#define OUT_F 64
#define SCAN_B 1024

// Scratch (bss, no runtime allocation)
__device__ int   g_cnt[NMAX];
__device__ int   g_scan[NMAX];
__device__ int   g_bsum[(NMAX + SCAN_B - 1) / SCAN_B];
__device__ int   g_rowptr[NMAX + 1];
__device__ int   g_cursor[NMAX];
__device__ int   g_csr_src[EMAX];
__device__ float g_csr_coef[EMAX];
__device__ float g_dinv[NMAX];
__device__ float g_h1[(size_t)NMAX * HID];
__device__ float g_agg1[(size_t)NMAX * HID];
__device__ float g_h2[(size_t)NMAX * OUT_F];

// ---------------------------------------------------------------------------
// CSR build: count -> scan -> rowptr/cursor -> fill
// ---------------------------------------------------------------------------
__global__ void k_cnt_init(int* cnt, int n) {
    int i = blockIdx.x * blockDim.x + threadIdx.x;
    if (i < n) cnt[i] = 0;
}

__global__ void k_cnt(const int* __restrict__ dst, int* cnt, int e) {
    int i = blockIdx.x * blockDim.x + threadIdx.x;
    if (i < e) atomicAdd(&cnt[dst[i]], 1);
}

__global__ void k_dinv(const int* __restrict__ cnt, float* dinv, int n) {
    int i = blockIdx.x * blockDim.x + threadIdx.x;
    if (i < n) dinv[i] = rsqrtf((float)(cnt[i] + 1));  // +1 self loop
}

__global__ void k_scan1(const int* __restrict__ cnt, int* scan, int* bsum, int n) {
    __shared__ int sh[SCAN_B];
    int i = blockIdx.x * SCAN_B + threadIdx.x;
    int v = (i < n) ? cnt[i] : 0;
    sh[threadIdx.x] = v;
    __syncthreads();
#pragma unroll
    for (int off = 1; off < SCAN_B; off <<= 1) {
        int t = (threadIdx.x >= off) ? sh[threadIdx.x - off] : 0;
        __syncthreads();
        sh[threadIdx.x] += t;
        __syncthreads();
    }
    if (i < n) scan[i] = sh[threadIdx.x];
    if (threadIdx.x == SCAN_B - 1) bsum[blockIdx.x] = sh[SCAN_B - 1];
}

__global__ void k_scan2(int* bsum, int nb) {
    __shared__ int sh[128];
    int v = (threadIdx.x < nb) ? bsum[threadIdx.x] : 0;
    sh[threadIdx.x] = v;
    __syncthreads();
#pragma unroll
    for (int off = 1; off < 128; off <<= 1) {
        int t = (threadIdx.x >= off) ? sh[threadIdx.x - off] : 0;
        __syncthreads();
        sh[threadIdx.x] += t;
        __syncthreads();
    }
    if (threadIdx.x < nb) bsum[threadIdx.x] = sh[threadIdx.x] - v;  // exclusive
}

__global__ void k_scan3(const int* __restrict__ cnt, const int* __restrict__ scan,
                        const int* __restrict__ bsum, int* rowptr, int* cursor, int n) {
    int i = blockIdx.x * blockDim.x + threadIdx.x;
    if (i >= n) return;
    int excl = scan[i] - cnt[i] + bsum[i / SCAN_B];
    rowptr[i] = excl;
    cursor[i] = excl;
    if (i == n - 1) rowptr[n] = excl + cnt[i];
}

__global__ void k_fill(const int* __restrict__ src, const int* __restrict__ dst,
                       const float* __restrict__ dinv, int* cursor,
                       int* __restrict__ csr_src, float* __restrict__ csr_coef, int e) {
    int i = blockIdx.x * blockDim.x + threadIdx.x;
    if (i >= e) return;
    int s = src[i];
    int d = dst[i];
    int pos = atomicAdd(&cursor[d], 1);
    csr_src[pos] = s;
    csr_coef[pos] = dinv[s] * dinv[d];
}

// ---------------------------------------------------------------------------
// Warp-per-node CSR aggregation (gather, no atomics)
// ---------------------------------------------------------------------------
__global__ void k_agg_csr128(const float* __restrict__ h,
                             const int* __restrict__ rowptr,
                             const int* __restrict__ csr_src,
                             const float* __restrict__ csr_coef,
                             const float* __restrict__ dinv,
                             float* __restrict__ out, int n) {
    int node = (blockIdx.x * blockDim.x + threadIdx.x) >> 5;
    int lane = threadIdx.x & 31;
    if (node >= n) return;
    float di = dinv[node];
    float4 v = *reinterpret_cast<const float4*>(h + (size_t)node * 128 + lane * 4);
    float c = di * di;
    float4 acc = make_float4(v.x * c, v.y * c, v.z * c, v.w * c);
    int idx = rowptr[node], end = rowptr[node + 1];
    for (; idx + 1 < end; idx += 2) {
        int s0 = csr_src[idx], s1 = csr_src[idx + 1];
        float c0 = csr_coef[idx], c1 = csr_coef[idx + 1];
        float4 v0 = *reinterpret_cast<const float4*>(h + (size_t)s0 * 128 + lane * 4);
        float4 v1 = *reinterpret_cast<const float4*>(h + (size_t)s1 * 128 + lane * 4);
        acc.x = fmaf(v0.x, c0, acc.x); acc.y = fmaf(v0.y, c0, acc.y);
        acc.z = fmaf(v0.z, c0, acc.z); acc.w = fmaf(v0.w, c0, acc.w);
        acc.x = fmaf(v1.x, c1, acc.x); acc.y = fmaf(v1.y, c1, acc.y);
        acc.z = fmaf(v1.z, c1, acc.z); acc.w = fmaf(v1.w, c1, acc.w);
    }
    if (idx < end) {
        int s0 = csr_src[idx];
        float c0 = csr_coef[idx];
        float4 v0 = *reinterpret_cast<const float4*>(h + (size_t)s0 * 128 + lane * 4);
        acc.x = fmaf(v0.x, c0, acc.x); acc.y = fmaf(v0.y, c0, acc.y);
        acc.z = fmaf(v0.z, c0, acc.z); acc.w = fmaf(v0.w, c0, acc.w);
    }
    *reinterpret_cast<float4*>(out + (size_t)node * 128 + lane * 4) = acc;
}

__global__ void k_agg_csr64(const float* __restrict__ h,
                            const int* __restrict__ rowptr,
                            const int* __restrict__ csr_src,
                            const float* __restrict__ csr_coef,
                            const float* __restrict__ dinv,
                            const float* __restrict__ bias,
                            float* __restrict__ out, int n) {
    int node = (blockIdx.x * blockDim.x + threadIdx.x) >> 5;
    int lane = threadIdx.x & 31;
    if (node >= n) return;
    float di = dinv[node];
    float2 v = *reinterpret_cast<const float2*>(h + (size_t)node * 64 + lane * 2);
    float c = di * di;
    float2 acc = make_float2(v.x * c, v.y * c);
    int idx = rowptr[node], end = rowptr[node + 1];
    for (; idx + 1 < end; idx += 2) {
        int s0 = csr_src[idx], s1 = csr_src[idx + 1];
        float c0 = csr_coef[idx], c1 = csr_coef[idx + 1];
        float2 v0 = *reinterpret_cast<const float2*>(h + (size_t)s0 * 64 + lane * 2);
        float2 v1 = *reinterpret_cast<const float2*>(h + (size_t)s1 * 64 + lane * 2);
        acc.x = fmaf(v0.x, c0, acc.x); acc.y = fmaf(v0.y, c0, acc.y);
        acc.x = fmaf(v1.x, c1, acc.x); acc.y = fmaf(v1.y, c1, acc.y);
    }
    if (idx < end) {
        int s0 = csr_src[idx];
        float c0 = csr_coef[idx];
        float2 v0 = *reinterpret_cast<const float2*>(h + (size_t)s0 * 64 + lane * 2);
        acc.x = fmaf(v0.x, c0, acc.x); acc.y = fmaf(v0.y, c0, acc.y);
    }
    float2 b = *reinterpret_cast<const float2*>(bias + lane * 2);
    acc.x += b.x;
    acc.y += b.y;
    *reinterpret_cast<float2*>(out + (size_t)node * 64 + lane * 2) = acc;
}

// ---------------------------------------------------------------------------
// Register-blocked SGEMM (unchanged from R1)
// ---------------------------------------------------------------------------
template <int BM, int BN, int BK, int TM, int TN, bool FUSE_RELU_BIAS>
__global__ void __launch_bounds__((BM / TM) * (BN / TN))
k_sgemm(int M, int N, int K,
        const float* __restrict__ A,
        const float* __restrict__ B,
        const float* __restrict__ biasA,
        float* __restrict__ C) {
    constexpr int THREADS = (BM / TM) * (BN / TN);
    __shared__ float As[BK][BM];
    __shared__ float Bs[BK][BN];

    const int block_row = blockIdx.x * BM;
    const int block_col = blockIdx.y * BN;
    const int tid = threadIdx.x;
    const int tcol = tid % (BN / TN);
    const int trow = tid / (BN / TN);

    float acc[TM][TN];
#pragma unroll
    for (int i = 0; i < TM; i++)
#pragma unroll
        for (int j = 0; j < TN; j++) acc[i][j] = 0.f;

    for (int k0 = 0; k0 < K; k0 += BK) {
#pragma unroll
        for (int i = tid * 4; i < BM * BK; i += THREADS * 4) {
            int m = i / BK;
            int kk = i % BK;
            int gr = block_row + m;
            float4 v = make_float4(0.f, 0.f, 0.f, 0.f);
            if (gr < M)
                v = *reinterpret_cast<const float4*>(A + (size_t)gr * K + k0 + kk);
            if (FUSE_RELU_BIAS) {
                v.x = fmaxf(v.x + biasA[k0 + kk + 0], 0.f);
                v.y = fmaxf(v.y + biasA[k0 + kk + 1], 0.f);
                v.z = fmaxf(v.z + biasA[k0 + kk + 2], 0.f);
                v.w = fmaxf(v.w + biasA[k0 + kk + 3], 0.f);
            }
            As[kk + 0][m] = v.x;
            As[kk + 1][m] = v.y;
            As[kk + 2][m] = v.z;
            As[kk + 3][m] = v.w;
        }
#pragma unroll
        for (int i = tid * 4; i < BK * BN; i += THREADS * 4) {
            int kk = i / BN;
            int nn = i % BN;
            float4 v = *reinterpret_cast<const float4*>(
                B + (size_t)(k0 + kk) * N + block_col + nn);
            *reinterpret_cast<float4*>(&Bs[kk][nn]) = v;
        }
        __syncthreads();

        float regM[TM], regN[TN];
#pragma unroll
        for (int k = 0; k < BK; k++) {
#pragma unroll
            for (int i = 0; i < TM; i++) regM[i] = As[k][trow * TM + i];
#pragma unroll
            for (int j = 0; j < TN; j++) regN[j] = Bs[k][tcol * TN + j];
#pragma unroll
            for (int i = 0; i < TM; i++)
#pragma unroll
                for (int j = 0; j < TN; j++)
                    acc[i][j] = fmaf(regM[i], regN[j], acc[i][j]);
        }
        __syncthreads();
    }

#pragma unroll
    for (int i = 0; i < TM; i++) {
        int gr = block_row + trow * TM + i;
        if (gr >= M) continue;
#pragma unroll
        for (int j = 0; j < TN; j += 4) {
            float4 v = make_float4(acc[i][j], acc[i][j + 1], acc[i][j + 2],
                                   acc[i][j + 3]);
            *reinterpret_cast<float4*>(C + (size_t)gr * N + block_col +
                                       tcol * TN + j) = v;
        }
    }
}

// ---------------------------------------------------------------------------
// Launch
// ---------------------------------------------------------------------------
extern "C" void kernel_launch(void* const* d_in, const int* in_sizes, int n_in,
                              void* d_out, int out_size) {
    const float* x = (const float*)d_in[0];
    const int* ei = (const int*)d_in[1];
    const float* W1 = (const float*)d_in[2];
    const float* b1 = (const float*)d_in[3];
    const float* W2 = (const float*)d_in[4];
    const float* b2 = (const float*)d_in[5];
    float* out = (float*)d_out;

    const int n = in_sizes[0] / IN_F;  // 100000
    const int e = in_sizes[1] / 2;     // 1600000
    const int* src = ei;
    const int* dst = ei + e;
    const int nb = (n + SCAN_B - 1) / SCAN_B;

    int *p_cnt, *p_scan, *p_bsum, *p_rowptr, *p_cursor, *p_csr_src;
    float *p_csr_coef, *p_dinv, *p_h1, *p_agg1, *p_h2;
    cudaGetSymbolAddress((void**)&p_cnt, g_cnt);
    cudaGetSymbolAddress((void**)&p_scan, g_scan);
    cudaGetSymbolAddress((void**)&p_bsum, g_bsum);
    cudaGetSymbolAddress((void**)&p_rowptr, g_rowptr);
    cudaGetSymbolAddress((void**)&p_cursor, g_cursor);
    cudaGetSymbolAddress((void**)&p_csr_src, g_csr_src);
    cudaGetSymbolAddress((void**)&p_csr_coef, g_csr_coef);
    cudaGetSymbolAddress((void**)&p_dinv, g_dinv);
    cudaGetSymbolAddress((void**)&p_h1, g_h1);
    cudaGetSymbolAddress((void**)&p_agg1, g_agg1);
    cudaGetSymbolAddress((void**)&p_h2, g_h2);

    // --- CSR build
    k_cnt_init<<<(n + 255) / 256, 256>>>(p_cnt, n);
    k_cnt<<<(e + 255) / 256, 256>>>(dst, p_cnt, e);
    k_dinv<<<(n + 255) / 256, 256>>>(p_cnt, p_dinv, n);
    k_scan1<<<nb, SCAN_B>>>(p_cnt, p_scan, p_bsum, n);
    k_scan2<<<1, 128>>>(p_bsum, nb);
    k_scan3<<<(n + 255) / 256, 256>>>(p_cnt, p_scan, p_bsum, p_rowptr, p_cursor, n);
    k_fill<<<(e + 255) / 256, 256>>>(src, dst, p_dinv, p_cursor, p_csr_src,
                                     p_csr_coef, e);

    // --- GEMM1: h1 = x @ W1
    {
        constexpr int BM = 128, BN = 128, BK = 16, TM = 8, TN = 8;
        dim3 grid((n + BM - 1) / BM, (HID + BN - 1) / BN);
        k_sgemm<BM, BN, BK, TM, TN, false>
            <<<grid, (BM / TM) * (BN / TN)>>>(n, HID, IN_F, x, W1, nullptr, p_h1);
    }

    // --- Layer-1 aggregation (gather, warp per node)
    k_agg_csr128<<<(n * 32 + 255) / 256, 256>>>(p_h1, p_rowptr, p_csr_src,
                                                p_csr_coef, p_dinv, p_agg1, n);

    // --- GEMM2: h2 = relu(agg1 + b1) @ W2
    {
        constexpr int BM = 128, BN = 64, BK = 16, TM = 8, TN = 4;
        dim3 grid((n + BM - 1) / BM, (OUT_F + BN - 1) / BN);
        k_sgemm<BM, BN, BK, TM, TN, true>
            <<<grid, (BM / TM) * (BN / TN)>>>(n, OUT_F, HID, p_agg1, W2, b1, p_h2);
    }

    // --- Layer-2 aggregation into d_out (+ b2)
    k_agg_csr64<<<(n * 32 + 255) / 256, 256>>>(p_h2, p_rowptr, p_csr_src,
                                               p_csr_coef, p_dinv, b2, out, n);
}

// round 5
// speedup vs baseline: 2.9256x; 1.2012x over previous
#include <cuda_runtime.h>
#include <cuda_bf16.h>
#include <cstdint>

#define NMAX 100000
#define EMAX 1600000
#define IN_F 256
#define HID 128
#define OUT_F 64
#define SCAN_B 1024

// ---------------------------------------------------------------------------
// Scratch (bss, no runtime allocation)
// ---------------------------------------------------------------------------
__device__ int   g_cnt[NMAX];
__device__ int   g_scan[NMAX];
__device__ int   g_bsum[(NMAX + SCAN_B - 1) / SCAN_B];
__device__ int   g_rowptr[NMAX + 1];
__device__ int   g_cursor[NMAX];
__device__ __align__(16) int   g_csr_src[EMAX];
__device__ __align__(16) float g_csr_coef[EMAX];
__device__ float g_dinv[NMAX];
__device__ __align__(128) float g_h1[(size_t)NMAX * HID];
__device__ __align__(128) float g_agg1[(size_t)NMAX * HID];
__device__ __align__(128) float g_h2[(size_t)NMAX * OUT_F];
__device__ __align__(128) float g_w1t_hi[HID * IN_F];   // tf32(W1^T)
__device__ __align__(128) float g_w1t_lo[HID * IN_F];   // tf32(W1^T - hi)
__device__ __align__(128) float g_w2t_hi[OUT_F * HID];
__device__ __align__(128) float g_w2t_lo[OUT_F * HID];

// ---------------------------------------------------------------------------
// PTX helpers (baseline PTX only)
// ---------------------------------------------------------------------------
__device__ __forceinline__ uint32_t smem_u32(const void* p) {
    uint32_t a;
    asm("{ .reg .u64 t; cvta.to.shared.u64 t, %1; cvt.u32.u64 %0, t; }"
        : "=r"(a) : "l"(p));
    return a;
}
__device__ __forceinline__ void cp_async16(uint32_t sa, const void* g) {
    asm volatile("cp.async.cg.shared.global [%0], [%1], 16;" ::"r"(sa), "l"(g));
}
__device__ __forceinline__ void cp_commit() {
    asm volatile("cp.async.commit_group;");
}
template <int N>
__device__ __forceinline__ void cp_wait() {
    asm volatile("cp.async.wait_group %0;" ::"n"(N));
}
__device__ __forceinline__ void ldsm_x4(uint32_t& r0, uint32_t& r1, uint32_t& r2,
                                        uint32_t& r3, uint32_t addr) {
    asm volatile("ldmatrix.sync.aligned.m8n8.x4.shared.b16 {%0,%1,%2,%3}, [%4];"
                 : "=r"(r0), "=r"(r1), "=r"(r2), "=r"(r3) : "r"(addr));
}
__device__ __forceinline__ uint32_t f2tf32(float v) {
    uint32_t r;
    asm("cvt.rna.tf32.f32 %0, %1;" : "=r"(r) : "f"(v));
    return r;
}
__device__ __forceinline__ void mma_tf32(float* c, const uint32_t* a,
                                         const uint32_t* b) {
    asm volatile(
        "mma.sync.aligned.m16n8k8.row.col.f32.tf32.tf32.f32 "
        "{%0,%1,%2,%3}, {%4,%5,%6,%7}, {%8,%9}, {%0,%1,%2,%3};"
        : "+f"(c[0]), "+f"(c[1]), "+f"(c[2]), "+f"(c[3])
        : "r"(a[0]), "r"(a[1]), "r"(a[2]), "r"(a[3]), "r"(b[0]), "r"(b[1]));
}

// ---------------------------------------------------------------------------
// 3xTF32 mma.sync GEMM:  C[M,NT] = A[M,KT] @ BT[NT,KT]^T
// CTA: 256 thr (8 warps 4x2), block tile 128 x NT, BK=16, 2-stage cp.async.
// D = Ah*Bh + Al*Bh + Ah*Bl  (split tf32, ~fp32 precision)
// Shared rows: 16 floats + 4 pad (80B) — 16B aligned, ldmatrix conflict-free.
// ---------------------------------------------------------------------------
template <int NT, int KT>
__global__ void __launch_bounds__(256)
k_mma_gemm(int M, const float* __restrict__ A, const float* __restrict__ BTh,
           const float* __restrict__ BTl, float* __restrict__ C) {
    constexpr int BK = 16;
    constexpr int T = KT / BK;
    constexpr int STRIDE_B = 80;
    constexpr int A_ST = 128 * STRIDE_B;
    constexpr int B_ST = NT * STRIDE_B;
    constexpr int STAGE = A_ST + 2 * B_ST;
    constexpr int NFRAG = NT / 16;  // n8 frags per warp (warp covers NT/2 cols)

    extern __shared__ __align__(16) char smem[];
    const uint32_t sb = smem_u32(smem);
    const int tid = threadIdx.x;
    const int wid = tid >> 5, lane = tid & 31;
    const int warpM = wid >> 1, warpN = wid & 1;
    const int brow = blockIdx.x * 128;

    float acc[2][NFRAG][4];
#pragma unroll
    for (int i = 0; i < 2; i++)
#pragma unroll
        for (int j = 0; j < NFRAG; j++)
#pragma unroll
            for (int q = 0; q < 4; q++) acc[i][j][q] = 0.f;

    auto prefetch = [&](int t, int s) {
        const uint32_t ao = sb + s * STAGE;
        const uint32_t bho = ao + A_ST;
        const uint32_t blo = bho + B_ST;
#pragma unroll
        for (int c = tid; c < 128 * 4; c += 256) {
            int m = c >> 2, qi = c & 3;
            int gr = brow + m;
            if (gr >= M) gr = M - 1;
            cp_async16(ao + m * STRIDE_B + qi * 16,
                       A + (size_t)gr * KT + t * BK + qi * 4);
        }
#pragma unroll
        for (int c = tid; c < NT * 4; c += 256) {
            int r = c >> 2, qi = c & 3;
            cp_async16(bho + r * STRIDE_B + qi * 16,
                       BTh + (size_t)r * KT + t * BK + qi * 4);
            cp_async16(blo + r * STRIDE_B + qi * 16,
                       BTl + (size_t)r * KT + t * BK + qi * 4);
        }
        cp_commit();
    };

    prefetch(0, 0);
    prefetch(1, 1);

    const int ti = lane >> 3, ri = lane & 7;

    for (int t = 0; t < T; t++) {
        const int s = t & 1;
        // last tile has no younger group in flight -> must drain fully
        if (t + 1 < T) cp_wait<1>(); else cp_wait<0>();
        __syncthreads();

        const uint32_t ao = sb + s * STAGE;
        const uint32_t bho = ao + A_ST;
        const uint32_t blo = bho + B_ST;

#pragma unroll
        for (int ks = 0; ks < 2; ks++) {
            const int k0 = ks * 8;
            // --- A fragments: raw, split hi/lo
            uint32_t ar[2][4], ah[2][4], al[2][4];
#pragma unroll
            for (int f = 0; f < 2; f++) {
                int m = warpM * 32 + f * 16 + (ti & 1) * 8 + ri;
                uint32_t addr = ao + m * STRIDE_B + (k0 + (ti >> 1) * 4) * 4;
                ldsm_x4(ar[f][0], ar[f][1], ar[f][2], ar[f][3], addr);
#pragma unroll
                for (int q = 0; q < 4; q++) {
                    float raw = __uint_as_float(ar[f][q]);
                    ah[f][q] = f2tf32(raw);
                    al[f][q] = f2tf32(raw - __uint_as_float(ah[f][q]));
                }
            }
            // --- B fragments hi & lo (pre-split weights)
            uint32_t bh[NFRAG][2], bl[NFRAG][2];
#pragma unroll
            for (int fp = 0; fp < NFRAG / 2; fp++) {
                int n = warpN * (NT / 2) + fp * 16 + (ti >> 1) * 8 + ri;
                uint32_t off = n * STRIDE_B + (k0 + (ti & 1) * 4) * 4;
                ldsm_x4(bh[2 * fp][0], bh[2 * fp][1], bh[2 * fp + 1][0],
                        bh[2 * fp + 1][1], bho + off);
                ldsm_x4(bl[2 * fp][0], bl[2 * fp][1], bl[2 * fp + 1][0],
                        bl[2 * fp + 1][1], blo + off);
            }
            // --- 3xTF32 MMAs
#pragma unroll
            for (int mf = 0; mf < 2; mf++)
#pragma unroll
                for (int nf = 0; nf < NFRAG; nf++) {
                    mma_tf32(acc[mf][nf], al[mf], bh[nf]);
                    mma_tf32(acc[mf][nf], ah[mf], bl[nf]);
                    mma_tf32(acc[mf][nf], ah[mf], bh[nf]);
                }
        }
        __syncthreads();
        if (t + 2 < T) prefetch(t + 2, s);
    }

    // --- epilogue
#pragma unroll
    for (int mf = 0; mf < 2; mf++) {
        int row0 = brow + warpM * 32 + mf * 16 + (lane >> 2);
        int row1 = row0 + 8;
#pragma unroll
        for (int nf = 0; nf < NFRAG; nf++) {
            int col = warpN * (NT / 2) + nf * 8 + (lane & 3) * 2;
            if (row0 < M)
                *reinterpret_cast<float2*>(C + (size_t)row0 * NT + col) =
                    make_float2(acc[mf][nf][0], acc[mf][nf][1]);
            if (row1 < M)
                *reinterpret_cast<float2*>(C + (size_t)row1 * NT + col) =
                    make_float2(acc[mf][nf][2], acc[mf][nf][3]);
        }
    }
}

// ---------------------------------------------------------------------------
// Weight transpose + hi/lo tf32 split
// ---------------------------------------------------------------------------
__global__ void k_transpose_split(const float* __restrict__ W,
                                  float* __restrict__ WTh,
                                  float* __restrict__ WTl, int K, int N) {
    int i = blockIdx.x * blockDim.x + threadIdx.x;
    if (i >= K * N) return;
    int k = i / N, nn = i % N;
    float w = W[i];
    uint32_t hb = f2tf32(w);
    float hi = __uint_as_float(hb);
    uint32_t lb = f2tf32(w - hi);
    WTh[(size_t)nn * K + k] = hi;
    WTl[(size_t)nn * K + k] = __uint_as_float(lb);
}

// ---------------------------------------------------------------------------
// CSR build: count -> scan -> rowptr/cursor -> fill
// ---------------------------------------------------------------------------
__global__ void k_cnt_init(int* cnt, int n) {
    int i = blockIdx.x * blockDim.x + threadIdx.x;
    if (i < n) cnt[i] = 0;
}
__global__ void k_cnt(const int* __restrict__ dst, int* cnt, int e) {
    int i = blockIdx.x * blockDim.x + threadIdx.x;
    if (i < e) atomicAdd(&cnt[dst[i]], 1);
}
__global__ void k_dinv(const int* __restrict__ cnt, float* dinv, int n) {
    int i = blockIdx.x * blockDim.x + threadIdx.x;
    if (i < n) dinv[i] = rsqrtf((float)(cnt[i] + 1));
}
__global__ void k_scan1(const int* __restrict__ cnt, int* scan, int* bsum, int n) {
    __shared__ int sh[SCAN_B];
    int i = blockIdx.x * SCAN_B + threadIdx.x;
    int v = (i < n) ? cnt[i] : 0;
    sh[threadIdx.x] = v;
    __syncthreads();
#pragma unroll
    for (int off = 1; off < SCAN_B; off <<= 1) {
        int t = (threadIdx.x >= off) ? sh[threadIdx.x - off] : 0;
        __syncthreads();
        sh[threadIdx.x] += t;
        __syncthreads();
    }
    if (i < n) scan[i] = sh[threadIdx.x];
    if (threadIdx.x == SCAN_B - 1) bsum[blockIdx.x] = sh[SCAN_B - 1];
}
__global__ void k_scan2(int* bsum, int nb) {
    __shared__ int sh[128];
    int v = (threadIdx.x < nb) ? bsum[threadIdx.x] : 0;
    sh[threadIdx.x] = v;
    __syncthreads();
#pragma unroll
    for (int off = 1; off < 128; off <<= 1) {
        int t = (threadIdx.x >= off) ? sh[threadIdx.x - off] : 0;
        __syncthreads();
        sh[threadIdx.x] += t;
        __syncthreads();
    }
    if (threadIdx.x < nb) bsum[threadIdx.x] = sh[threadIdx.x] - v;
}
__global__ void k_scan3(const int* __restrict__ cnt, const int* __restrict__ scan,
                        const int* __restrict__ bsum, int* rowptr, int* cursor, int n) {
    int i = blockIdx.x * blockDim.x + threadIdx.x;
    if (i >= n) return;
    int excl = scan[i] - cnt[i] + bsum[i / SCAN_B];
    rowptr[i] = excl;
    cursor[i] = excl;
    if (i == n - 1) rowptr[n] = excl + cnt[i];
}
__global__ void k_fill(const int* __restrict__ src, const int* __restrict__ dst,
                       const float* __restrict__ dinv, int* cursor,
                       int* __restrict__ csr_src, float* __restrict__ csr_coef, int e) {
    int i = blockIdx.x * blockDim.x + threadIdx.x;
    if (i >= e) return;
    int s = src[i];
    int d = dst[i];
    int pos = atomicAdd(&cursor[d], 1);
    csr_src[pos] = s;
    csr_coef[pos] = dinv[s] * dinv[d];
}

// ---------------------------------------------------------------------------
// Warp-per-node CSR aggregation (gather). F=128 fuses +b1 and relu.
// ---------------------------------------------------------------------------
__global__ void k_agg_csr128(const float* __restrict__ h,
                             const int* __restrict__ rowptr,
                             const int* __restrict__ csr_src,
                             const float* __restrict__ csr_coef,
                             const float* __restrict__ dinv,
                             const float* __restrict__ b1,
                             float* __restrict__ out, int n) {
    int node = (blockIdx.x * blockDim.x + threadIdx.x) >> 5;
    int lane = threadIdx.x & 31;
    if (node >= n) return;
    float di = dinv[node];
    float4 v = *reinterpret_cast<const float4*>(h + (size_t)node * 128 + lane * 4);
    float c = di * di;
    float4 acc = make_float4(v.x * c, v.y * c, v.z * c, v.w * c);
    int idx = rowptr[node], end = rowptr[node + 1];
    for (; idx + 1 < end; idx += 2) {
        int s0 = csr_src[idx], s1 = csr_src[idx + 1];
        float c0 = csr_coef[idx], c1 = csr_coef[idx + 1];
        float4 v0 = *reinterpret_cast<const float4*>(h + (size_t)s0 * 128 + lane * 4);
        float4 v1 = *reinterpret_cast<const float4*>(h + (size_t)s1 * 128 + lane * 4);
        acc.x = fmaf(v0.x, c0, acc.x); acc.y = fmaf(v0.y, c0, acc.y);
        acc.z = fmaf(v0.z, c0, acc.z); acc.w = fmaf(v0.w, c0, acc.w);
        acc.x = fmaf(v1.x, c1, acc.x); acc.y = fmaf(v1.y, c1, acc.y);
        acc.z = fmaf(v1.z, c1, acc.z); acc.w = fmaf(v1.w, c1, acc.w);
    }
    if (idx < end) {
        int s0 = csr_src[idx];
        float c0 = csr_coef[idx];
        float4 v0 = *reinterpret_cast<const float4*>(h + (size_t)s0 * 128 + lane * 4);
        acc.x = fmaf(v0.x, c0, acc.x); acc.y = fmaf(v0.y, c0, acc.y);
        acc.z = fmaf(v0.z, c0, acc.z); acc.w = fmaf(v0.w, c0, acc.w);
    }
    float4 b = *reinterpret_cast<const float4*>(b1 + lane * 4);
    acc.x = fmaxf(acc.x + b.x, 0.f);
    acc.y = fmaxf(acc.y + b.y, 0.f);
    acc.z = fmaxf(acc.z + b.z, 0.f);
    acc.w = fmaxf(acc.w + b.w, 0.f);
    *reinterpret_cast<float4*>(out + (size_t)node * 128 + lane * 4) = acc;
}

__global__ void k_agg_csr64(const float* __restrict__ h,
                            const int* __restrict__ rowptr,
                            const int* __restrict__ csr_src,
                            const float* __restrict__ csr_coef,
                            const float* __restrict__ dinv,
                            const float* __restrict__ bias,
                            float* __restrict__ out, int n) {
    int node = (blockIdx.x * blockDim.x + threadIdx.x) >> 5;
    int lane = threadIdx.x & 31;
    if (node >= n) return;
    float di = dinv[node];
    float2 v = *reinterpret_cast<const float2*>(h + (size_t)node * 64 + lane * 2);
    float c = di * di;
    float2 acc = make_float2(v.x * c, v.y * c);
    int idx = rowptr[node], end = rowptr[node + 1];
    for (; idx + 1 < end; idx += 2) {
        int s0 = csr_src[idx], s1 = csr_src[idx + 1];
        float c0 = csr_coef[idx], c1 = csr_coef[idx + 1];
        float2 v0 = *reinterpret_cast<const float2*>(h + (size_t)s0 * 64 + lane * 2);
        float2 v1 = *reinterpret_cast<const float2*>(h + (size_t)s1 * 64 + lane * 2);
        acc.x = fmaf(v0.x, c0, acc.x); acc.y = fmaf(v0.y, c0, acc.y);
        acc.x = fmaf(v1.x, c1, acc.x); acc.y = fmaf(v1.y, c1, acc.y);
    }
    if (idx < end) {
        int s0 = csr_src[idx];
        float c0 = csr_coef[idx];
        float2 v0 = *reinterpret_cast<const float2*>(h + (size_t)s0 * 64 + lane * 2);
        acc.x = fmaf(v0.x, c0, acc.x); acc.y = fmaf(v0.y, c0, acc.y);
    }
    float2 b = *reinterpret_cast<const float2*>(bias + lane * 2);
    acc.x += b.x;
    acc.y += b.y;
    *reinterpret_cast<float2*>(out + (size_t)node * 64 + lane * 2) = acc;
}

// ---------------------------------------------------------------------------
// Launch
// ---------------------------------------------------------------------------
extern "C" void kernel_launch(void* const* d_in, const int* in_sizes, int n_in,
                              void* d_out, int out_size) {
    const float* x = (const float*)d_in[0];
    const int* ei = (const int*)d_in[1];
    const float* W1 = (const float*)d_in[2];
    const float* b1 = (const float*)d_in[3];
    const float* W2 = (const float*)d_in[4];
    const float* b2 = (const float*)d_in[5];
    float* out = (float*)d_out;

    const int n = in_sizes[0] / IN_F;  // 100000
    const int e = in_sizes[1] / 2;     // 1600000
    const int* src = ei;
    const int* dst = ei + e;
    const int nb = (n + SCAN_B - 1) / SCAN_B;

    int *p_cnt, *p_scan, *p_bsum, *p_rowptr, *p_cursor, *p_csr_src;
    float *p_csr_coef, *p_dinv, *p_h1, *p_agg1, *p_h2;
    float *p_w1h, *p_w1l, *p_w2h, *p_w2l;
    cudaGetSymbolAddress((void**)&p_cnt, g_cnt);
    cudaGetSymbolAddress((void**)&p_scan, g_scan);
    cudaGetSymbolAddress((void**)&p_bsum, g_bsum);
    cudaGetSymbolAddress((void**)&p_rowptr, g_rowptr);
    cudaGetSymbolAddress((void**)&p_cursor, g_cursor);
    cudaGetSymbolAddress((void**)&p_csr_src, g_csr_src);
    cudaGetSymbolAddress((void**)&p_csr_coef, g_csr_coef);
    cudaGetSymbolAddress((void**)&p_dinv, g_dinv);
    cudaGetSymbolAddress((void**)&p_h1, g_h1);
    cudaGetSymbolAddress((void**)&p_agg1, g_agg1);
    cudaGetSymbolAddress((void**)&p_h2, g_h2);
    cudaGetSymbolAddress((void**)&p_w1h, g_w1t_hi);
    cudaGetSymbolAddress((void**)&p_w1l, g_w1t_lo);
    cudaGetSymbolAddress((void**)&p_w2h, g_w2t_hi);
    cudaGetSymbolAddress((void**)&p_w2l, g_w2t_lo);

    // --- weight split-transposes + CSR build
    k_transpose_split<<<(IN_F * HID + 255) / 256, 256>>>(W1, p_w1h, p_w1l, IN_F, HID);
    k_transpose_split<<<(HID * OUT_F + 255) / 256, 256>>>(W2, p_w2h, p_w2l, HID, OUT_F);
    k_cnt_init<<<(n + 255) / 256, 256>>>(p_cnt, n);
    k_cnt<<<(e + 255) / 256, 256>>>(dst, p_cnt, e);
    k_dinv<<<(n + 255) / 256, 256>>>(p_cnt, p_dinv, n);
    k_scan1<<<nb, SCAN_B>>>(p_cnt, p_scan, p_bsum, n);
    k_scan2<<<1, 128>>>(p_bsum, nb);
    k_scan3<<<(n + 255) / 256, 256>>>(p_cnt, p_scan, p_bsum, p_rowptr, p_cursor, n);
    k_fill<<<(e + 255) / 256, 256>>>(src, dst, p_dinv, p_cursor, p_csr_src,
                                     p_csr_coef, e);

    const int grid_m = (n + 127) / 128;

    // --- GEMM1: h1 = x @ W1 (3xTF32 mma.sync), dynamic smem
    {
        constexpr int SMEM1 = 2 * (128 * 80 + 2 * HID * 80);  // 61440
        cudaFuncSetAttribute(k_mma_gemm<HID, IN_F>,
                             cudaFuncAttributeMaxDynamicSharedMemorySize, SMEM1);
        k_mma_gemm<HID, IN_F><<<grid_m, 256, SMEM1>>>(n, x, p_w1h, p_w1l, p_h1);
    }

    // --- Layer-1 aggregation + b1 + relu
    k_agg_csr128<<<(n * 32 + 255) / 256, 256>>>(p_h1, p_rowptr, p_csr_src,
                                                p_csr_coef, p_dinv, b1, p_agg1, n);

    // --- GEMM2: h2 = agg1 @ W2 (3xTF32 mma.sync)
    {
        constexpr int SMEM2 = 2 * (128 * 80 + 2 * OUT_F * 80);  // 40960
        cudaFuncSetAttribute(k_mma_gemm<OUT_F, HID>,
                             cudaFuncAttributeMaxDynamicSharedMemorySize, SMEM2);
        k_mma_gemm<OUT_F, HID><<<grid_m, 256, SMEM2>>>(n, p_agg1, p_w2h, p_w2l, p_h2);
    }

    // --- Layer-2 aggregation into d_out (+ b2)
    k_agg_csr64<<<(n * 32 + 255) / 256, 256>>>(p_h2, p_rowptr, p_csr_src,
                                               p_csr_coef, p_dinv, b2, out, n);
}

// round 6
// speedup vs baseline: 2.9727x; 1.0161x over previous
#include <cuda_runtime.h>
#include <cuda_bf16.h>
#include <cstdint>

#define NMAX 100000
#define EMAX 1600000
#define IN_F 256
#define HID 128
#define OUT_F 64
#define SCAN_B 1024

// ---------------------------------------------------------------------------
// Scratch (bss, no runtime allocation)
// ---------------------------------------------------------------------------
__device__ int   g_cnt[NMAX];
__device__ int   g_scan[NMAX];
__device__ int   g_bsum[(NMAX + SCAN_B - 1) / SCAN_B];
__device__ int   g_rowptr[NMAX + 1];
__device__ int   g_cursor[NMAX];
__device__ __align__(16) int   g_csr_src[EMAX];
__device__ __align__(16) float g_csr_coef[EMAX];
__device__ float g_dinv[NMAX];
__device__ __align__(128) float g_h1[(size_t)NMAX * HID];
__device__ __align__(128) float g_agg1[(size_t)NMAX * HID];
__device__ __align__(128) float g_h2[(size_t)NMAX * OUT_F];
__device__ __align__(128) float g_w1t_hi[HID * IN_F];
__device__ __align__(128) float g_w1t_lo[HID * IN_F];
__device__ __align__(128) float g_w2t_hi[OUT_F * HID];
__device__ __align__(128) float g_w2t_lo[OUT_F * HID];

// ---------------------------------------------------------------------------
// PTX helpers (baseline PTX only)
// ---------------------------------------------------------------------------
__device__ __forceinline__ uint32_t smem_u32(const void* p) {
    uint32_t a;
    asm("{ .reg .u64 t; cvta.to.shared.u64 t, %1; cvt.u32.u64 %0, t; }"
        : "=r"(a) : "l"(p));
    return a;
}
__device__ __forceinline__ void cp_async16(uint32_t sa, const void* g) {
    asm volatile("cp.async.cg.shared.global [%0], [%1], 16;" ::"r"(sa), "l"(g));
}
__device__ __forceinline__ void cp_commit() {
    asm volatile("cp.async.commit_group;");
}
template <int N>
__device__ __forceinline__ void cp_wait() {
    asm volatile("cp.async.wait_group %0;" ::"n"(N));
}
__device__ __forceinline__ void ldsm_x4(uint32_t& r0, uint32_t& r1, uint32_t& r2,
                                        uint32_t& r3, uint32_t addr) {
    asm volatile("ldmatrix.sync.aligned.m8n8.x4.shared.b16 {%0,%1,%2,%3}, [%4];"
                 : "=r"(r0), "=r"(r1), "=r"(r2), "=r"(r3) : "r"(addr));
}
__device__ __forceinline__ uint32_t f2tf32(float v) {
    uint32_t r;
    asm("cvt.rna.tf32.f32 %0, %1;" : "=r"(r) : "f"(v));
    return r;
}
__device__ __forceinline__ void mma_tf32(float* c, const uint32_t* a,
                                         const uint32_t* b) {
    asm volatile(
        "mma.sync.aligned.m16n8k8.row.col.f32.tf32.tf32.f32 "
        "{%0,%1,%2,%3}, {%4,%5,%6,%7}, {%8,%9}, {%0,%1,%2,%3};"
        : "+f"(c[0]), "+f"(c[1]), "+f"(c[2]), "+f"(c[3])
        : "r"(a[0]), "r"(a[1]), "r"(a[2]), "r"(a[3]), "r"(b[0]), "r"(b[1]));
}

// ---------------------------------------------------------------------------
// 3xTF32 mma.sync GEMM, 3-stage cp.async pipeline, single sync per k-tile.
// C[M,NT] = A[M,KT] @ BT[NT,KT]^T  with D = Ah*Bh + Al*Bh + Ah*Bl.
// ---------------------------------------------------------------------------
template <int NT, int KT>
__global__ void __launch_bounds__(256)
k_mma_gemm(int M, const float* __restrict__ A, const float* __restrict__ BTh,
           const float* __restrict__ BTl, float* __restrict__ C) {
    constexpr int BK = 16;
    constexpr int T = KT / BK;
    constexpr int STRIDE_B = 80;
    constexpr int A_ST = 128 * STRIDE_B;
    constexpr int B_ST = NT * STRIDE_B;
    constexpr int STAGE = A_ST + 2 * B_ST;
    constexpr int NFRAG = NT / 16;

    extern __shared__ __align__(16) char smem[];
    const uint32_t sb = smem_u32(smem);
    const int tid = threadIdx.x;
    const int wid = tid >> 5, lane = tid & 31;
    const int warpM = wid >> 1, warpN = wid & 1;
    const int brow = blockIdx.x * 128;

    float acc[2][NFRAG][4];
#pragma unroll
    for (int i = 0; i < 2; i++)
#pragma unroll
        for (int j = 0; j < NFRAG; j++)
#pragma unroll
            for (int q = 0; q < 4; q++) acc[i][j][q] = 0.f;

    auto prefetch = [&](int t, int s) {
        const uint32_t ao = sb + s * STAGE;
        const uint32_t bho = ao + A_ST;
        const uint32_t blo = bho + B_ST;
#pragma unroll
        for (int c = tid; c < 128 * 4; c += 256) {
            int m = c >> 2, qi = c & 3;
            int gr = brow + m;
            if (gr >= M) gr = M - 1;
            cp_async16(ao + m * STRIDE_B + qi * 16,
                       A + (size_t)gr * KT + t * BK + qi * 4);
        }
#pragma unroll
        for (int c = tid; c < NT * 4; c += 256) {
            int r = c >> 2, qi = c & 3;
            cp_async16(bho + r * STRIDE_B + qi * 16,
                       BTh + (size_t)r * KT + t * BK + qi * 4);
            cp_async16(blo + r * STRIDE_B + qi * 16,
                       BTl + (size_t)r * KT + t * BK + qi * 4);
        }
        cp_commit();
    };

    prefetch(0, 0);
    if (T > 1) prefetch(1, 1);

    const int ti = lane >> 3, ri = lane & 7;

    for (int t = 0; t < T; t++) {
        const int s = t % 3;
        // G(t) must be complete; younger committed groups: 1 unless last tile
        if (t + 1 < T) cp_wait<1>(); else cp_wait<0>();
        __syncthreads();  // also proves compute(t-1) done -> stage (t-1)%3 free
        if (t + 2 < T) prefetch(t + 2, (t + 2) % 3);

        const uint32_t ao = sb + s * STAGE;
        const uint32_t bho = ao + A_ST;
        const uint32_t blo = bho + B_ST;

#pragma unroll
        for (int ks = 0; ks < 2; ks++) {
            const int k0 = ks * 8;
            uint32_t ar[2][4], ah[2][4], al[2][4];
#pragma unroll
            for (int f = 0; f < 2; f++) {
                int m = warpM * 32 + f * 16 + (ti & 1) * 8 + ri;
                uint32_t addr = ao + m * STRIDE_B + (k0 + (ti >> 1) * 4) * 4;
                ldsm_x4(ar[f][0], ar[f][1], ar[f][2], ar[f][3], addr);
#pragma unroll
                for (int q = 0; q < 4; q++) {
                    float raw = __uint_as_float(ar[f][q]);
                    ah[f][q] = f2tf32(raw);
                    al[f][q] = f2tf32(raw - __uint_as_float(ah[f][q]));
                }
            }
            uint32_t bh[NFRAG][2], bl[NFRAG][2];
#pragma unroll
            for (int fp = 0; fp < NFRAG / 2; fp++) {
                int n = warpN * (NT / 2) + fp * 16 + (ti >> 1) * 8 + ri;
                uint32_t off = n * STRIDE_B + (k0 + (ti & 1) * 4) * 4;
                ldsm_x4(bh[2 * fp][0], bh[2 * fp][1], bh[2 * fp + 1][0],
                        bh[2 * fp + 1][1], bho + off);
                ldsm_x4(bl[2 * fp][0], bl[2 * fp][1], bl[2 * fp + 1][0],
                        bl[2 * fp + 1][1], blo + off);
            }
#pragma unroll
            for (int mf = 0; mf < 2; mf++)
#pragma unroll
                for (int nf = 0; nf < NFRAG; nf++) {
                    mma_tf32(acc[mf][nf], al[mf], bh[nf]);
                    mma_tf32(acc[mf][nf], ah[mf], bl[nf]);
                    mma_tf32(acc[mf][nf], ah[mf], bh[nf]);
                }
        }
    }

#pragma unroll
    for (int mf = 0; mf < 2; mf++) {
        int row0 = brow + warpM * 32 + mf * 16 + (lane >> 2);
        int row1 = row0 + 8;
#pragma unroll
        for (int nf = 0; nf < NFRAG; nf++) {
            int col = warpN * (NT / 2) + nf * 8 + (lane & 3) * 2;
            if (row0 < M)
                *reinterpret_cast<float2*>(C + (size_t)row0 * NT + col) =
                    make_float2(acc[mf][nf][0], acc[mf][nf][1]);
            if (row1 < M)
                *reinterpret_cast<float2*>(C + (size_t)row1 * NT + col) =
                    make_float2(acc[mf][nf][2], acc[mf][nf][3]);
        }
    }
}

// ---------------------------------------------------------------------------
// Weight transpose + hi/lo tf32 split
// ---------------------------------------------------------------------------
__global__ void k_transpose_split(const float* __restrict__ W,
                                  float* __restrict__ WTh,
                                  float* __restrict__ WTl, int K, int N) {
    int i = blockIdx.x * blockDim.x + threadIdx.x;
    if (i >= K * N) return;
    int k = i / N, nn = i % N;
    float w = W[i];
    uint32_t hb = f2tf32(w);
    float hi = __uint_as_float(hb);
    uint32_t lb = f2tf32(w - hi);
    WTh[(size_t)nn * K + k] = hi;
    WTl[(size_t)nn * K + k] = __uint_as_float(lb);
}

// ---------------------------------------------------------------------------
// CSR build (side stream): count -> scan -> rowptr/cursor -> fill
// ---------------------------------------------------------------------------
__global__ void k_cnt(const int* __restrict__ dst, int* cnt, int e) {
    int i = blockIdx.x * blockDim.x + threadIdx.x;
    int base = i * 4;
    if (base + 3 < e) {
        int4 d = *reinterpret_cast<const int4*>(dst + base);
        atomicAdd(&cnt[d.x], 1);
        atomicAdd(&cnt[d.y], 1);
        atomicAdd(&cnt[d.z], 1);
        atomicAdd(&cnt[d.w], 1);
    } else {
        for (int j = base; j < e; j++) atomicAdd(&cnt[dst[j]], 1);
    }
}
__global__ void k_dinv(const int* __restrict__ cnt, float* dinv, int n) {
    int i = blockIdx.x * blockDim.x + threadIdx.x;
    if (i < n) dinv[i] = rsqrtf((float)(cnt[i] + 1));
}
__global__ void k_scan1(const int* __restrict__ cnt, int* scan, int* bsum, int n) {
    __shared__ int sh[SCAN_B];
    int i = blockIdx.x * SCAN_B + threadIdx.x;
    int v = (i < n) ? cnt[i] : 0;
    sh[threadIdx.x] = v;
    __syncthreads();
#pragma unroll
    for (int off = 1; off < SCAN_B; off <<= 1) {
        int t = (threadIdx.x >= off) ? sh[threadIdx.x - off] : 0;
        __syncthreads();
        sh[threadIdx.x] += t;
        __syncthreads();
    }
    if (i < n) scan[i] = sh[threadIdx.x];
    if (threadIdx.x == SCAN_B - 1) bsum[blockIdx.x] = sh[SCAN_B - 1];
}
__global__ void k_scan2(int* bsum, int nb) {
    __shared__ int sh[128];
    int v = (threadIdx.x < nb) ? bsum[threadIdx.x] : 0;
    sh[threadIdx.x] = v;
    __syncthreads();
#pragma unroll
    for (int off = 1; off < 128; off <<= 1) {
        int t = (threadIdx.x >= off) ? sh[threadIdx.x - off] : 0;
        __syncthreads();
        sh[threadIdx.x] += t;
        __syncthreads();
    }
    if (threadIdx.x < nb) bsum[threadIdx.x] = sh[threadIdx.x] - v;
}
__global__ void k_scan3(const int* __restrict__ cnt, const int* __restrict__ scan,
                        const int* __restrict__ bsum, int* rowptr, int* cursor, int n) {
    int i = blockIdx.x * blockDim.x + threadIdx.x;
    if (i >= n) return;
    int excl = scan[i] - cnt[i] + bsum[i / SCAN_B];
    rowptr[i] = excl;
    cursor[i] = excl;
    if (i == n - 1) rowptr[n] = excl + cnt[i];
}
__global__ void k_fill(const int* __restrict__ src, const int* __restrict__ dst,
                       const float* __restrict__ dinv, int* cursor,
                       int* __restrict__ csr_src, float* __restrict__ csr_coef, int e) {
    int i = blockIdx.x * blockDim.x + threadIdx.x;
    int base = i * 4;
    if (base + 3 < e) {
        int4 sv = *reinterpret_cast<const int4*>(src + base);
        int4 dv = *reinterpret_cast<const int4*>(dst + base);
        const int ss[4] = {sv.x, sv.y, sv.z, sv.w};
        const int dd[4] = {dv.x, dv.y, dv.z, dv.w};
#pragma unroll
        for (int j = 0; j < 4; j++) {
            int pos = atomicAdd(&cursor[dd[j]], 1);
            csr_src[pos] = ss[j];
            csr_coef[pos] = dinv[ss[j]] * dinv[dd[j]];
        }
    } else {
        for (int j = base; j < e; j++) {
            int s = src[j], d = dst[j];
            int pos = atomicAdd(&cursor[d], 1);
            csr_src[pos] = s;
            csr_coef[pos] = dinv[s] * dinv[d];
        }
    }
}

// ---------------------------------------------------------------------------
// Warp-per-node CSR aggregation (gather). F=128 fuses +b1 and relu.
// ---------------------------------------------------------------------------
__global__ void k_agg_csr128(const float* __restrict__ h,
                             const int* __restrict__ rowptr,
                             const int* __restrict__ csr_src,
                             const float* __restrict__ csr_coef,
                             const float* __restrict__ dinv,
                             const float* __restrict__ b1,
                             float* __restrict__ out, int n) {
    int node = (blockIdx.x * blockDim.x + threadIdx.x) >> 5;
    int lane = threadIdx.x & 31;
    if (node >= n) return;
    float di = dinv[node];
    float4 v = *reinterpret_cast<const float4*>(h + (size_t)node * 128 + lane * 4);
    float c = di * di;
    float4 acc = make_float4(v.x * c, v.y * c, v.z * c, v.w * c);
    int idx = rowptr[node], end = rowptr[node + 1];
    for (; idx + 1 < end; idx += 2) {
        int s0 = csr_src[idx], s1 = csr_src[idx + 1];
        float c0 = csr_coef[idx], c1 = csr_coef[idx + 1];
        float4 v0 = *reinterpret_cast<const float4*>(h + (size_t)s0 * 128 + lane * 4);
        float4 v1 = *reinterpret_cast<const float4*>(h + (size_t)s1 * 128 + lane * 4);
        acc.x = fmaf(v0.x, c0, acc.x); acc.y = fmaf(v0.y, c0, acc.y);
        acc.z = fmaf(v0.z, c0, acc.z); acc.w = fmaf(v0.w, c0, acc.w);
        acc.x = fmaf(v1.x, c1, acc.x); acc.y = fmaf(v1.y, c1, acc.y);
        acc.z = fmaf(v1.z, c1, acc.z); acc.w = fmaf(v1.w, c1, acc.w);
    }
    if (idx < end) {
        int s0 = csr_src[idx];
        float c0 = csr_coef[idx];
        float4 v0 = *reinterpret_cast<const float4*>(h + (size_t)s0 * 128 + lane * 4);
        acc.x = fmaf(v0.x, c0, acc.x); acc.y = fmaf(v0.y, c0, acc.y);
        acc.z = fmaf(v0.z, c0, acc.z); acc.w = fmaf(v0.w, c0, acc.w);
    }
    float4 b = *reinterpret_cast<const float4*>(b1 + lane * 4);
    acc.x = fmaxf(acc.x + b.x, 0.f);
    acc.y = fmaxf(acc.y + b.y, 0.f);
    acc.z = fmaxf(acc.z + b.z, 0.f);
    acc.w = fmaxf(acc.w + b.w, 0.f);
    *reinterpret_cast<float4*>(out + (size_t)node * 128 + lane * 4) = acc;
}

__global__ void k_agg_csr64(const float* __restrict__ h,
                            const int* __restrict__ rowptr,
                            const int* __restrict__ csr_src,
                            const float* __restrict__ csr_coef,
                            const float* __restrict__ dinv,
                            const float* __restrict__ bias,
                            float* __restrict__ out, int n) {
    int node = (blockIdx.x * blockDim.x + threadIdx.x) >> 5;
    int lane = threadIdx.x & 31;
    if (node >= n) return;
    float di = dinv[node];
    float2 v = *reinterpret_cast<const float2*>(h + (size_t)node * 64 + lane * 2);
    float c = di * di;
    float2 acc = make_float2(v.x * c, v.y * c);
    int idx = rowptr[node], end = rowptr[node + 1];
    for (; idx + 1 < end; idx += 2) {
        int s0 = csr_src[idx], s1 = csr_src[idx + 1];
        float c0 = csr_coef[idx], c1 = csr_coef[idx + 1];
        float2 v0 = *reinterpret_cast<const float2*>(h + (size_t)s0 * 64 + lane * 2);
        float2 v1 = *reinterpret_cast<const float2*>(h + (size_t)s1 * 64 + lane * 2);
        acc.x = fmaf(v0.x, c0, acc.x); acc.y = fmaf(v0.y, c0, acc.y);
        acc.x = fmaf(v1.x, c1, acc.x); acc.y = fmaf(v1.y, c1, acc.y);
    }
    if (idx < end) {
        int s0 = csr_src[idx];
        float c0 = csr_coef[idx];
        float2 v0 = *reinterpret_cast<const float2*>(h + (size_t)s0 * 64 + lane * 2);
        acc.x = fmaf(v0.x, c0, acc.x); acc.y = fmaf(v0.y, c0, acc.y);
    }
    float2 b = *reinterpret_cast<const float2*>(bias + lane * 2);
    acc.x += b.x;
    acc.y += b.y;
    *reinterpret_cast<float2*>(out + (size_t)node * 64 + lane * 2) = acc;
}

// ---------------------------------------------------------------------------
// Launch: fork CSR build onto side stream, GEMM1 on main, join before agg1.
// ---------------------------------------------------------------------------
extern "C" void kernel_launch(void* const* d_in, const int* in_sizes, int n_in,
                              void* d_out, int out_size) {
    const float* x = (const float*)d_in[0];
    const int* ei = (const int*)d_in[1];
    const float* W1 = (const float*)d_in[2];
    const float* b1 = (const float*)d_in[3];
    const float* W2 = (const float*)d_in[4];
    const float* b2 = (const float*)d_in[5];
    float* out = (float*)d_out;

    const int n = in_sizes[0] / IN_F;  // 100000
    const int e = in_sizes[1] / 2;     // 1600000
    const int* src = ei;
    const int* dst = ei + e;
    const int nb = (n + SCAN_B - 1) / SCAN_B;

    int *p_cnt, *p_scan, *p_bsum, *p_rowptr, *p_cursor, *p_csr_src;
    float *p_csr_coef, *p_dinv, *p_h1, *p_agg1, *p_h2;
    float *p_w1h, *p_w1l, *p_w2h, *p_w2l;
    cudaGetSymbolAddress((void**)&p_cnt, g_cnt);
    cudaGetSymbolAddress((void**)&p_scan, g_scan);
    cudaGetSymbolAddress((void**)&p_bsum, g_bsum);
    cudaGetSymbolAddress((void**)&p_rowptr, g_rowptr);
    cudaGetSymbolAddress((void**)&p_cursor, g_cursor);
    cudaGetSymbolAddress((void**)&p_csr_src, g_csr_src);
    cudaGetSymbolAddress((void**)&p_csr_coef, g_csr_coef);
    cudaGetSymbolAddress((void**)&p_dinv, g_dinv);
    cudaGetSymbolAddress((void**)&p_h1, g_h1);
    cudaGetSymbolAddress((void**)&p_agg1, g_agg1);
    cudaGetSymbolAddress((void**)&p_h2, g_h2);
    cudaGetSymbolAddress((void**)&p_w1h, g_w1t_hi);
    cudaGetSymbolAddress((void**)&p_w1l, g_w1t_lo);
    cudaGetSymbolAddress((void**)&p_w2h, g_w2t_hi);
    cudaGetSymbolAddress((void**)&p_w2l, g_w2t_lo);

    // One-time host resources (created on first, non-captured call)
    static cudaStream_t s2 = nullptr;
    static cudaEvent_t evFork = nullptr, evJoin = nullptr;
    if (s2 == nullptr) {
        cudaStreamCreateWithFlags(&s2, cudaStreamNonBlocking);
        cudaEventCreateWithFlags(&evFork, cudaEventDisableTiming);
        cudaEventCreateWithFlags(&evJoin, cudaEventDisableTiming);
    }

    // ---- fork: CSR build on side stream
    cudaEventRecord(evFork, 0);
    cudaStreamWaitEvent(s2, evFork, 0);
    cudaMemsetAsync(p_cnt, 0, (size_t)n * sizeof(int), s2);
    k_cnt<<<(e / 4 + 255) / 256, 256, 0, s2>>>(dst, p_cnt, e);
    k_dinv<<<(n + 255) / 256, 256, 0, s2>>>(p_cnt, p_dinv, n);
    k_scan1<<<nb, SCAN_B, 0, s2>>>(p_cnt, p_scan, p_bsum, n);
    k_scan2<<<1, 128, 0, s2>>>(p_bsum, nb);
    k_scan3<<<(n + 255) / 256, 256, 0, s2>>>(p_cnt, p_scan, p_bsum, p_rowptr,
                                             p_cursor, n);
    k_fill<<<(e / 4 + 255) / 256, 256, 0, s2>>>(src, dst, p_dinv, p_cursor,
                                                p_csr_src, p_csr_coef, e);
    cudaEventRecord(evJoin, s2);

    // ---- main stream: weight split-transposes + GEMM1
    k_transpose_split<<<(IN_F * HID + 255) / 256, 256>>>(W1, p_w1h, p_w1l, IN_F, HID);
    k_transpose_split<<<(HID * OUT_F + 255) / 256, 256>>>(W2, p_w2h, p_w2l, HID, OUT_F);

    const int grid_m = (n + 127) / 128;
    {
        constexpr int SMEM1 = 3 * (128 * 80 + 2 * HID * 80);  // 92160
        cudaFuncSetAttribute(k_mma_gemm<HID, IN_F>,
                             cudaFuncAttributeMaxDynamicSharedMemorySize, SMEM1);
        k_mma_gemm<HID, IN_F><<<grid_m, 256, SMEM1>>>(n, x, p_w1h, p_w1l, p_h1);
    }

    // ---- join: aggregation needs the CSR
    cudaStreamWaitEvent(0, evJoin, 0);

    k_agg_csr128<<<(n * 32 + 255) / 256, 256>>>(p_h1, p_rowptr, p_csr_src,
                                                p_csr_coef, p_dinv, b1, p_agg1, n);

    {
        constexpr int SMEM2 = 3 * (128 * 80 + 2 * OUT_F * 80);  // 61440
        cudaFuncSetAttribute(k_mma_gemm<OUT_F, HID>,
                             cudaFuncAttributeMaxDynamicSharedMemorySize, SMEM2);
        k_mma_gemm<OUT_F, HID><<<grid_m, 256, SMEM2>>>(n, p_agg1, p_w2h, p_w2l, p_h2);
    }

    k_agg_csr64<<<(n * 32 + 255) / 256, 256>>>(p_h2, p_rowptr, p_csr_src,
                                               p_csr_coef, p_dinv, b2, out, n);
}

// round 7
// speedup vs baseline: 3.0453x; 1.0244x over previous
#include <cuda_runtime.h>
#include <cuda_fp16.h>
#include <cuda_bf16.h>
#include <cstdint>

#define NMAX 100000
#define EMAX 1600000
#define IN_F 256
#define HID 128
#define OUT_F 64
#define SCAN_B 1024

// ---------------------------------------------------------------------------
// Scratch (bss, no runtime allocation)
// ---------------------------------------------------------------------------
__device__ int   g_cnt[NMAX];
__device__ int   g_scan[NMAX];
__device__ int   g_bsum[(NMAX + SCAN_B - 1) / SCAN_B];
__device__ int   g_rowptr[NMAX + 1];
__device__ int   g_cursor[NMAX];
__device__ __align__(16) int2  g_csr[EMAX];        // {src, coef-bits}
__device__ float g_dinv[NMAX];
__device__ __align__(128) __half g_h1[(size_t)NMAX * HID];   // fp16 h1
__device__ __align__(128) float  g_agg1[(size_t)NMAX * HID]; // fp32 (GEMM2 A)
__device__ __align__(128) float  g_h2[(size_t)NMAX * OUT_F];
__device__ __align__(128) float g_w1t_hi[HID * IN_F];
__device__ __align__(128) float g_w1t_lo[HID * IN_F];
__device__ __align__(128) float g_w2t_hi[OUT_F * HID];
__device__ __align__(128) float g_w2t_lo[OUT_F * HID];

// ---------------------------------------------------------------------------
// PTX helpers (baseline PTX only)
// ---------------------------------------------------------------------------
__device__ __forceinline__ uint32_t smem_u32(const void* p) {
    uint32_t a;
    asm("{ .reg .u64 t; cvta.to.shared.u64 t, %1; cvt.u32.u64 %0, t; }"
        : "=r"(a) : "l"(p));
    return a;
}
__device__ __forceinline__ void cp_async16(uint32_t sa, const void* g) {
    asm volatile("cp.async.cg.shared.global [%0], [%1], 16;" ::"r"(sa), "l"(g));
}
__device__ __forceinline__ void cp_commit() {
    asm volatile("cp.async.commit_group;");
}
template <int N>
__device__ __forceinline__ void cp_wait() {
    asm volatile("cp.async.wait_group %0;" ::"n"(N));
}
__device__ __forceinline__ void ldsm_x4(uint32_t& r0, uint32_t& r1, uint32_t& r2,
                                        uint32_t& r3, uint32_t addr) {
    asm volatile("ldmatrix.sync.aligned.m8n8.x4.shared.b16 {%0,%1,%2,%3}, [%4];"
                 : "=r"(r0), "=r"(r1), "=r"(r2), "=r"(r3) : "r"(addr));
}
__device__ __forceinline__ uint32_t f2tf32(float v) {
    uint32_t r;
    asm("cvt.rna.tf32.f32 %0, %1;" : "=r"(r) : "f"(v));
    return r;
}
__device__ __forceinline__ void mma_tf32(float* c, const uint32_t* a,
                                         const uint32_t* b) {
    asm volatile(
        "mma.sync.aligned.m16n8k8.row.col.f32.tf32.tf32.f32 "
        "{%0,%1,%2,%3}, {%4,%5,%6,%7}, {%8,%9}, {%0,%1,%2,%3};"
        : "+f"(c[0]), "+f"(c[1]), "+f"(c[2]), "+f"(c[3])
        : "r"(a[0]), "r"(a[1]), "r"(a[2]), "r"(a[3]), "r"(b[0]), "r"(b[1]));
}

// ---------------------------------------------------------------------------
// 3xTF32 mma.sync GEMM, 3-stage cp.async pipeline, single sync per k-tile.
// HALF_OUT: store C as fp16 (half2 pairs); else fp32.
// ---------------------------------------------------------------------------
template <int NT, int KT, bool HALF_OUT>
__global__ void __launch_bounds__(256)
k_mma_gemm(int M, const float* __restrict__ A, const float* __restrict__ BTh,
           const float* __restrict__ BTl, void* __restrict__ Cv) {
    constexpr int BK = 16;
    constexpr int T = KT / BK;
    constexpr int STRIDE_B = 80;
    constexpr int A_ST = 128 * STRIDE_B;
    constexpr int B_ST = NT * STRIDE_B;
    constexpr int STAGE = A_ST + 2 * B_ST;
    constexpr int NFRAG = NT / 16;

    extern __shared__ __align__(16) char smem[];
    const uint32_t sb = smem_u32(smem);
    const int tid = threadIdx.x;
    const int wid = tid >> 5, lane = tid & 31;
    const int warpM = wid >> 1, warpN = wid & 1;
    const int brow = blockIdx.x * 128;

    float acc[2][NFRAG][4];
#pragma unroll
    for (int i = 0; i < 2; i++)
#pragma unroll
        for (int j = 0; j < NFRAG; j++)
#pragma unroll
            for (int q = 0; q < 4; q++) acc[i][j][q] = 0.f;

    auto prefetch = [&](int t, int s) {
        const uint32_t ao = sb + s * STAGE;
        const uint32_t bho = ao + A_ST;
        const uint32_t blo = bho + B_ST;
#pragma unroll
        for (int c = tid; c < 128 * 4; c += 256) {
            int m = c >> 2, qi = c & 3;
            int gr = brow + m;
            if (gr >= M) gr = M - 1;
            cp_async16(ao + m * STRIDE_B + qi * 16,
                       A + (size_t)gr * KT + t * BK + qi * 4);
        }
#pragma unroll
        for (int c = tid; c < NT * 4; c += 256) {
            int r = c >> 2, qi = c & 3;
            cp_async16(bho + r * STRIDE_B + qi * 16,
                       BTh + (size_t)r * KT + t * BK + qi * 4);
            cp_async16(blo + r * STRIDE_B + qi * 16,
                       BTl + (size_t)r * KT + t * BK + qi * 4);
        }
        cp_commit();
    };

    prefetch(0, 0);
    if (T > 1) prefetch(1, 1);

    const int ti = lane >> 3, ri = lane & 7;

    for (int t = 0; t < T; t++) {
        const int s = t % 3;
        if (t + 1 < T) cp_wait<1>(); else cp_wait<0>();
        __syncthreads();
        if (t + 2 < T) prefetch(t + 2, (t + 2) % 3);

        const uint32_t ao = sb + s * STAGE;
        const uint32_t bho = ao + A_ST;
        const uint32_t blo = bho + B_ST;

#pragma unroll
        for (int ks = 0; ks < 2; ks++) {
            const int k0 = ks * 8;
            uint32_t ar[2][4], ah[2][4], al[2][4];
#pragma unroll
            for (int f = 0; f < 2; f++) {
                int m = warpM * 32 + f * 16 + (ti & 1) * 8 + ri;
                uint32_t addr = ao + m * STRIDE_B + (k0 + (ti >> 1) * 4) * 4;
                ldsm_x4(ar[f][0], ar[f][1], ar[f][2], ar[f][3], addr);
#pragma unroll
                for (int q = 0; q < 4; q++) {
                    float raw = __uint_as_float(ar[f][q]);
                    ah[f][q] = f2tf32(raw);
                    al[f][q] = f2tf32(raw - __uint_as_float(ah[f][q]));
                }
            }
            uint32_t bh[NFRAG][2], bl[NFRAG][2];
#pragma unroll
            for (int fp = 0; fp < NFRAG / 2; fp++) {
                int n = warpN * (NT / 2) + fp * 16 + (ti >> 1) * 8 + ri;
                uint32_t off = n * STRIDE_B + (k0 + (ti & 1) * 4) * 4;
                ldsm_x4(bh[2 * fp][0], bh[2 * fp][1], bh[2 * fp + 1][0],
                        bh[2 * fp + 1][1], bho + off);
                ldsm_x4(bl[2 * fp][0], bl[2 * fp][1], bl[2 * fp + 1][0],
                        bl[2 * fp + 1][1], blo + off);
            }
#pragma unroll
            for (int mf = 0; mf < 2; mf++)
#pragma unroll
                for (int nf = 0; nf < NFRAG; nf++) {
                    mma_tf32(acc[mf][nf], al[mf], bh[nf]);
                    mma_tf32(acc[mf][nf], ah[mf], bl[nf]);
                    mma_tf32(acc[mf][nf], ah[mf], bh[nf]);
                }
        }
    }

#pragma unroll
    for (int mf = 0; mf < 2; mf++) {
        int row0 = brow + warpM * 32 + mf * 16 + (lane >> 2);
        int row1 = row0 + 8;
#pragma unroll
        for (int nf = 0; nf < NFRAG; nf++) {
            int col = warpN * (NT / 2) + nf * 8 + (lane & 3) * 2;
            if (HALF_OUT) {
                __half* C = (__half*)Cv;
                if (row0 < M)
                    *reinterpret_cast<__half2*>(C + (size_t)row0 * NT + col) =
                        __floats2half2_rn(acc[mf][nf][0], acc[mf][nf][1]);
                if (row1 < M)
                    *reinterpret_cast<__half2*>(C + (size_t)row1 * NT + col) =
                        __floats2half2_rn(acc[mf][nf][2], acc[mf][nf][3]);
            } else {
                float* C = (float*)Cv;
                if (row0 < M)
                    *reinterpret_cast<float2*>(C + (size_t)row0 * NT + col) =
                        make_float2(acc[mf][nf][0], acc[mf][nf][1]);
                if (row1 < M)
                    *reinterpret_cast<float2*>(C + (size_t)row1 * NT + col) =
                        make_float2(acc[mf][nf][2], acc[mf][nf][3]);
            }
        }
    }
}

// ---------------------------------------------------------------------------
// Weight transpose + hi/lo tf32 split
// ---------------------------------------------------------------------------
__global__ void k_transpose_split(const float* __restrict__ W,
                                  float* __restrict__ WTh,
                                  float* __restrict__ WTl, int K, int N) {
    int i = blockIdx.x * blockDim.x + threadIdx.x;
    if (i >= K * N) return;
    int k = i / N, nn = i % N;
    float w = W[i];
    uint32_t hb = f2tf32(w);
    float hi = __uint_as_float(hb);
    uint32_t lb = f2tf32(w - hi);
    WTh[(size_t)nn * K + k] = hi;
    WTl[(size_t)nn * K + k] = __uint_as_float(lb);
}

// ---------------------------------------------------------------------------
// CSR build (side stream)
// ---------------------------------------------------------------------------
__global__ void k_cnt(const int* __restrict__ dst, int* cnt, int e) {
    int i = blockIdx.x * blockDim.x + threadIdx.x;
    int base = i * 4;
    if (base + 3 < e) {
        int4 d = *reinterpret_cast<const int4*>(dst + base);
        atomicAdd(&cnt[d.x], 1);
        atomicAdd(&cnt[d.y], 1);
        atomicAdd(&cnt[d.z], 1);
        atomicAdd(&cnt[d.w], 1);
    } else {
        for (int j = base; j < e; j++) atomicAdd(&cnt[dst[j]], 1);
    }
}
__global__ void k_dinv(const int* __restrict__ cnt, float* dinv, int n) {
    int i = blockIdx.x * blockDim.x + threadIdx.x;
    if (i < n) dinv[i] = rsqrtf((float)(cnt[i] + 1));
}
__global__ void k_scan1(const int* __restrict__ cnt, int* scan, int* bsum, int n) {
    __shared__ int sh[SCAN_B];
    int i = blockIdx.x * SCAN_B + threadIdx.x;
    int v = (i < n) ? cnt[i] : 0;
    sh[threadIdx.x] = v;
    __syncthreads();
#pragma unroll
    for (int off = 1; off < SCAN_B; off <<= 1) {
        int t = (threadIdx.x >= off) ? sh[threadIdx.x - off] : 0;
        __syncthreads();
        sh[threadIdx.x] += t;
        __syncthreads();
    }
    if (i < n) scan[i] = sh[threadIdx.x];
    if (threadIdx.x == SCAN_B - 1) bsum[blockIdx.x] = sh[SCAN_B - 1];
}
__global__ void k_scan2(int* bsum, int nb) {
    __shared__ int sh[128];
    int v = (threadIdx.x < nb) ? bsum[threadIdx.x] : 0;
    sh[threadIdx.x] = v;
    __syncthreads();
#pragma unroll
    for (int off = 1; off < 128; off <<= 1) {
        int t = (threadIdx.x >= off) ? sh[threadIdx.x - off] : 0;
        __syncthreads();
        sh[threadIdx.x] += t;
        __syncthreads();
    }
    if (threadIdx.x < nb) bsum[threadIdx.x] = sh[threadIdx.x] - v;
}
__global__ void k_scan3(const int* __restrict__ cnt, const int* __restrict__ scan,
                        const int* __restrict__ bsum, int* rowptr, int* cursor, int n) {
    int i = blockIdx.x * blockDim.x + threadIdx.x;
    if (i >= n) return;
    int excl = scan[i] - cnt[i] + bsum[i / SCAN_B];
    rowptr[i] = excl;
    cursor[i] = excl;
    if (i == n - 1) rowptr[n] = excl + cnt[i];
}
__global__ void k_fill(const int* __restrict__ src, const int* __restrict__ dst,
                       const float* __restrict__ dinv, int* cursor,
                       int2* __restrict__ csr, int e) {
    int i = blockIdx.x * blockDim.x + threadIdx.x;
    int base = i * 4;
    if (base + 3 < e) {
        int4 sv = *reinterpret_cast<const int4*>(src + base);
        int4 dv = *reinterpret_cast<const int4*>(dst + base);
        const int ss[4] = {sv.x, sv.y, sv.z, sv.w};
        const int dd[4] = {dv.x, dv.y, dv.z, dv.w};
#pragma unroll
        for (int j = 0; j < 4; j++) {
            int pos = atomicAdd(&cursor[dd[j]], 1);
            csr[pos] = make_int2(ss[j],
                                 __float_as_int(dinv[ss[j]] * dinv[dd[j]]));
        }
    } else {
        for (int j = base; j < e; j++) {
            int s = src[j], d = dst[j];
            int pos = atomicAdd(&cursor[d], 1);
            csr[pos] = make_int2(s, __float_as_int(dinv[s] * dinv[d]));
        }
    }
}

// ---------------------------------------------------------------------------
// Warp-per-node aggregation. agg1: h fp16 gather, +b1+relu, fp32 out.
// ---------------------------------------------------------------------------
__global__ void k_agg_csr128(const __half* __restrict__ h,
                             const int* __restrict__ rowptr,
                             const int2* __restrict__ csr,
                             const float* __restrict__ dinv,
                             const float* __restrict__ b1,
                             float* __restrict__ out, int n) {
    int node = (blockIdx.x * blockDim.x + threadIdx.x) >> 5;
    int lane = threadIdx.x & 31;
    if (node >= n) return;
    float di = dinv[node];
    float c = di * di;
    uint2 raw = *reinterpret_cast<const uint2*>(h + (size_t)node * 128 + lane * 4);
    float2 p0 = __half22float2(*reinterpret_cast<const __half2*>(&raw.x));
    float2 p1 = __half22float2(*reinterpret_cast<const __half2*>(&raw.y));
    float4 acc = make_float4(p0.x * c, p0.y * c, p1.x * c, p1.y * c);
    int idx = rowptr[node], end = rowptr[node + 1];
    for (; idx + 1 < end; idx += 2) {
        int2 e0 = csr[idx];
        int2 e1 = csr[idx + 1];
        float c0 = __int_as_float(e0.y);
        float c1 = __int_as_float(e1.y);
        uint2 r0 = *reinterpret_cast<const uint2*>(h + (size_t)e0.x * 128 + lane * 4);
        uint2 r1 = *reinterpret_cast<const uint2*>(h + (size_t)e1.x * 128 + lane * 4);
        float2 a0 = __half22float2(*reinterpret_cast<const __half2*>(&r0.x));
        float2 a1 = __half22float2(*reinterpret_cast<const __half2*>(&r0.y));
        float2 b0 = __half22float2(*reinterpret_cast<const __half2*>(&r1.x));
        float2 b1v = __half22float2(*reinterpret_cast<const __half2*>(&r1.y));
        acc.x = fmaf(a0.x, c0, acc.x); acc.y = fmaf(a0.y, c0, acc.y);
        acc.z = fmaf(a1.x, c0, acc.z); acc.w = fmaf(a1.y, c0, acc.w);
        acc.x = fmaf(b0.x, c1, acc.x); acc.y = fmaf(b0.y, c1, acc.y);
        acc.z = fmaf(b1v.x, c1, acc.z); acc.w = fmaf(b1v.y, c1, acc.w);
    }
    if (idx < end) {
        int2 e0 = csr[idx];
        float c0 = __int_as_float(e0.y);
        uint2 r0 = *reinterpret_cast<const uint2*>(h + (size_t)e0.x * 128 + lane * 4);
        float2 a0 = __half22float2(*reinterpret_cast<const __half2*>(&r0.x));
        float2 a1 = __half22float2(*reinterpret_cast<const __half2*>(&r0.y));
        acc.x = fmaf(a0.x, c0, acc.x); acc.y = fmaf(a0.y, c0, acc.y);
        acc.z = fmaf(a1.x, c0, acc.z); acc.w = fmaf(a1.y, c0, acc.w);
    }
    float4 b = *reinterpret_cast<const float4*>(b1 + lane * 4);
    acc.x = fmaxf(acc.x + b.x, 0.f);
    acc.y = fmaxf(acc.y + b.y, 0.f);
    acc.z = fmaxf(acc.z + b.z, 0.f);
    acc.w = fmaxf(acc.w + b.w, 0.f);
    *reinterpret_cast<float4*>(out + (size_t)node * 128 + lane * 4) = acc;
}

__global__ void k_agg_csr64(const float* __restrict__ h,
                            const int* __restrict__ rowptr,
                            const int2* __restrict__ csr,
                            const float* __restrict__ dinv,
                            const float* __restrict__ bias,
                            float* __restrict__ out, int n) {
    int node = (blockIdx.x * blockDim.x + threadIdx.x) >> 5;
    int lane = threadIdx.x & 31;
    if (node >= n) return;
    float di = dinv[node];
    float2 v = *reinterpret_cast<const float2*>(h + (size_t)node * 64 + lane * 2);
    float c = di * di;
    float2 acc = make_float2(v.x * c, v.y * c);
    int idx = rowptr[node], end = rowptr[node + 1];
    for (; idx + 1 < end; idx += 2) {
        int2 e0 = csr[idx];
        int2 e1 = csr[idx + 1];
        float c0 = __int_as_float(e0.y);
        float c1 = __int_as_float(e1.y);
        float2 v0 = *reinterpret_cast<const float2*>(h + (size_t)e0.x * 64 + lane * 2);
        float2 v1 = *reinterpret_cast<const float2*>(h + (size_t)e1.x * 64 + lane * 2);
        acc.x = fmaf(v0.x, c0, acc.x); acc.y = fmaf(v0.y, c0, acc.y);
        acc.x = fmaf(v1.x, c1, acc.x); acc.y = fmaf(v1.y, c1, acc.y);
    }
    if (idx < end) {
        int2 e0 = csr[idx];
        float c0 = __int_as_float(e0.y);
        float2 v0 = *reinterpret_cast<const float2*>(h + (size_t)e0.x * 64 + lane * 2);
        acc.x = fmaf(v0.x, c0, acc.x); acc.y = fmaf(v0.y, c0, acc.y);
    }
    float2 b = *reinterpret_cast<const float2*>(bias + lane * 2);
    acc.x += b.x;
    acc.y += b.y;
    *reinterpret_cast<float2*>(out + (size_t)node * 64 + lane * 2) = acc;
}

// ---------------------------------------------------------------------------
// Launch
// ---------------------------------------------------------------------------
extern "C" void kernel_launch(void* const* d_in, const int* in_sizes, int n_in,
                              void* d_out, int out_size) {
    const float* x = (const float*)d_in[0];
    const int* ei = (const int*)d_in[1];
    const float* W1 = (const float*)d_in[2];
    const float* b1 = (const float*)d_in[3];
    const float* W2 = (const float*)d_in[4];
    const float* b2 = (const float*)d_in[5];
    float* out = (float*)d_out;

    const int n = in_sizes[0] / IN_F;  // 100000
    const int e = in_sizes[1] / 2;     // 1600000
    const int* src = ei;
    const int* dst = ei + e;
    const int nb = (n + SCAN_B - 1) / SCAN_B;

    int *p_cnt, *p_scan, *p_bsum, *p_rowptr, *p_cursor;
    int2* p_csr;
    float *p_dinv, *p_agg1, *p_h2;
    __half* p_h1;
    float *p_w1h, *p_w1l, *p_w2h, *p_w2l;
    cudaGetSymbolAddress((void**)&p_cnt, g_cnt);
    cudaGetSymbolAddress((void**)&p_scan, g_scan);
    cudaGetSymbolAddress((void**)&p_bsum, g_bsum);
    cudaGetSymbolAddress((void**)&p_rowptr, g_rowptr);
    cudaGetSymbolAddress((void**)&p_cursor, g_cursor);
    cudaGetSymbolAddress((void**)&p_csr, g_csr);
    cudaGetSymbolAddress((void**)&p_dinv, g_dinv);
    cudaGetSymbolAddress((void**)&p_h1, g_h1);
    cudaGetSymbolAddress((void**)&p_agg1, g_agg1);
    cudaGetSymbolAddress((void**)&p_h2, g_h2);
    cudaGetSymbolAddress((void**)&p_w1h, g_w1t_hi);
    cudaGetSymbolAddress((void**)&p_w1l, g_w1t_lo);
    cudaGetSymbolAddress((void**)&p_w2h, g_w2t_hi);
    cudaGetSymbolAddress((void**)&p_w2l, g_w2t_lo);

    static cudaStream_t s2 = nullptr;
    static cudaEvent_t evFork = nullptr, evJoin = nullptr;
    if (s2 == nullptr) {
        cudaStreamCreateWithFlags(&s2, cudaStreamNonBlocking);
        cudaEventCreateWithFlags(&evFork, cudaEventDisableTiming);
        cudaEventCreateWithFlags(&evJoin, cudaEventDisableTiming);
    }

    // ---- fork: CSR build on side stream
    cudaEventRecord(evFork, 0);
    cudaStreamWaitEvent(s2, evFork, 0);
    cudaMemsetAsync(p_cnt, 0, (size_t)n * sizeof(int), s2);
    k_cnt<<<(e / 4 + 255) / 256, 256, 0, s2>>>(dst, p_cnt, e);
    k_dinv<<<(n + 255) / 256, 256, 0, s2>>>(p_cnt, p_dinv, n);
    k_scan1<<<nb, SCAN_B, 0, s2>>>(p_cnt, p_scan, p_bsum, n);
    k_scan2<<<1, 128, 0, s2>>>(p_bsum, nb);
    k_scan3<<<(n + 255) / 256, 256, 0, s2>>>(p_cnt, p_scan, p_bsum, p_rowptr,
                                             p_cursor, n);
    k_fill<<<(e / 4 + 255) / 256, 256, 0, s2>>>(src, dst, p_dinv, p_cursor,
                                                p_csr, e);
    cudaEventRecord(evJoin, s2);

    // ---- main stream: weight split-transposes + GEMM1 (fp16 out)
    k_transpose_split<<<(IN_F * HID + 255) / 256, 256>>>(W1, p_w1h, p_w1l, IN_F, HID);
    k_transpose_split<<<(HID * OUT_F + 255) / 256, 256>>>(W2, p_w2h, p_w2l, HID, OUT_F);

    const int grid_m = (n + 127) / 128;
    {
        constexpr int SMEM1 = 3 * (128 * 80 + 2 * HID * 80);  // 92160
        cudaFuncSetAttribute(k_mma_gemm<HID, IN_F, true>,
                             cudaFuncAttributeMaxDynamicSharedMemorySize, SMEM1);
        k_mma_gemm<HID, IN_F, true><<<grid_m, 256, SMEM1>>>(n, x, p_w1h, p_w1l,
                                                            p_h1);
    }

    // ---- join: aggregation needs the CSR
    cudaStreamWaitEvent(0, evJoin, 0);

    k_agg_csr128<<<(n * 32 + 255) / 256, 256>>>(p_h1, p_rowptr, p_csr, p_dinv,
                                                b1, p_agg1, n);

    {
        constexpr int SMEM2 = 3 * (128 * 80 + 2 * OUT_F * 80);  // 61440
        cudaFuncSetAttribute(k_mma_gemm<OUT_F, HID, false>,
                             cudaFuncAttributeMaxDynamicSharedMemorySize, SMEM2);
        k_mma_gemm<OUT_F, HID, false><<<grid_m, 256, SMEM2>>>(n, p_agg1, p_w2h,
                                                              p_w2l, p_h2);
    }

    k_agg_csr64<<<(n * 32 + 255) / 256, 256>>>(p_h2, p_rowptr, p_csr, p_dinv,
                                               b2, out, n);
}

// round 8
// speedup vs baseline: 3.9569x; 1.2993x over previous
#include <cuda_runtime.h>
#include <cuda_fp16.h>
#include <cuda_bf16.h>
#include <cstdint>

#define NMAX 100000
#define EMAX 1600000
#define IN_F 256
#define HID 128
#define OUT_F 64
#define SCAN_B 1024

// ---------------------------------------------------------------------------
// Scratch (bss, no runtime allocation)
// ---------------------------------------------------------------------------
__device__ int   g_cnt[NMAX];
__device__ int   g_scan[NMAX];
__device__ int   g_bsum[(NMAX + SCAN_B - 1) / SCAN_B];
__device__ int   g_rowptr[NMAX + 1];
__device__ int   g_cursor[NMAX];
__device__ __align__(16) int2  g_csr[EMAX];        // {src, coef-bits}
__device__ float g_dinv[NMAX];
__device__ __align__(128) __half g_h1[(size_t)NMAX * HID];   // fp16 h1
__device__ __align__(128) float  g_agg1[(size_t)NMAX * HID]; // fp32 (GEMM2 A)
__device__ __align__(128) __half g_h2[(size_t)NMAX * OUT_F]; // fp16 h2
__device__ __align__(128) float g_w1t_hi[HID * IN_F];
__device__ __align__(128) float g_w1t_lo[HID * IN_F];
__device__ __align__(128) float g_w2t_hi[OUT_F * HID];
__device__ __align__(128) float g_w2t_lo[OUT_F * HID];

// ---------------------------------------------------------------------------
// PTX helpers (baseline PTX only)
// ---------------------------------------------------------------------------
__device__ __forceinline__ uint32_t smem_u32(const void* p) {
    uint32_t a;
    asm("{ .reg .u64 t; cvta.to.shared.u64 t, %1; cvt.u32.u64 %0, t; }"
        : "=r"(a) : "l"(p));
    return a;
}
__device__ __forceinline__ void cp_async16(uint32_t sa, const void* g) {
    asm volatile("cp.async.cg.shared.global [%0], [%1], 16;" ::"r"(sa), "l"(g));
}
__device__ __forceinline__ void cp_commit() {
    asm volatile("cp.async.commit_group;");
}
template <int N>
__device__ __forceinline__ void cp_wait() {
    asm volatile("cp.async.wait_group %0;" ::"n"(N));
}
__device__ __forceinline__ void ldsm_x4(uint32_t& r0, uint32_t& r1, uint32_t& r2,
                                        uint32_t& r3, uint32_t addr) {
    asm volatile("ldmatrix.sync.aligned.m8n8.x4.shared.b16 {%0,%1,%2,%3}, [%4];"
                 : "=r"(r0), "=r"(r1), "=r"(r2), "=r"(r3) : "r"(addr));
}
__device__ __forceinline__ uint32_t f2tf32(float v) {
    uint32_t r;
    asm("cvt.rna.tf32.f32 %0, %1;" : "=r"(r) : "f"(v));
    return r;
}
__device__ __forceinline__ void mma_tf32(float* c, const uint32_t* a,
                                         const uint32_t* b) {
    asm volatile(
        "mma.sync.aligned.m16n8k8.row.col.f32.tf32.tf32.f32 "
        "{%0,%1,%2,%3}, {%4,%5,%6,%7}, {%8,%9}, {%0,%1,%2,%3};"
        : "+f"(c[0]), "+f"(c[1]), "+f"(c[2]), "+f"(c[3])
        : "r"(a[0]), "r"(a[1]), "r"(a[2]), "r"(a[3]), "r"(b[0]), "r"(b[1]));
}

// ---------------------------------------------------------------------------
// 2-term TF32 mma.sync GEMM:  D = Ah*Bh + Ah*Bl  (A single-rounded, B split)
// 3-stage cp.async pipeline, single sync per k-tile.
// ---------------------------------------------------------------------------
template <int NT, int KT, bool HALF_OUT>
__global__ void __launch_bounds__(256)
k_mma_gemm(int M, const float* __restrict__ A, const float* __restrict__ BTh,
           const float* __restrict__ BTl, void* __restrict__ Cv) {
    constexpr int BK = 16;
    constexpr int T = KT / BK;
    constexpr int STRIDE_B = 80;
    constexpr int A_ST = 128 * STRIDE_B;
    constexpr int B_ST = NT * STRIDE_B;
    constexpr int STAGE = A_ST + 2 * B_ST;
    constexpr int NFRAG = NT / 16;

    extern __shared__ __align__(16) char smem[];
    const uint32_t sb = smem_u32(smem);
    const int tid = threadIdx.x;
    const int wid = tid >> 5, lane = tid & 31;
    const int warpM = wid >> 1, warpN = wid & 1;
    const int brow = blockIdx.x * 128;

    float acc[2][NFRAG][4];
#pragma unroll
    for (int i = 0; i < 2; i++)
#pragma unroll
        for (int j = 0; j < NFRAG; j++)
#pragma unroll
            for (int q = 0; q < 4; q++) acc[i][j][q] = 0.f;

    auto prefetch = [&](int t, int s) {
        const uint32_t ao = sb + s * STAGE;
        const uint32_t bho = ao + A_ST;
        const uint32_t blo = bho + B_ST;
#pragma unroll
        for (int c = tid; c < 128 * 4; c += 256) {
            int m = c >> 2, qi = c & 3;
            int gr = brow + m;
            if (gr >= M) gr = M - 1;
            cp_async16(ao + m * STRIDE_B + qi * 16,
                       A + (size_t)gr * KT + t * BK + qi * 4);
        }
#pragma unroll
        for (int c = tid; c < NT * 4; c += 256) {
            int r = c >> 2, qi = c & 3;
            cp_async16(bho + r * STRIDE_B + qi * 16,
                       BTh + (size_t)r * KT + t * BK + qi * 4);
            cp_async16(blo + r * STRIDE_B + qi * 16,
                       BTl + (size_t)r * KT + t * BK + qi * 4);
        }
        cp_commit();
    };

    prefetch(0, 0);
    if (T > 1) prefetch(1, 1);

    const int ti = lane >> 3, ri = lane & 7;

    for (int t = 0; t < T; t++) {
        const int s = t % 3;
        if (t + 1 < T) cp_wait<1>(); else cp_wait<0>();
        __syncthreads();
        if (t + 2 < T) prefetch(t + 2, (t + 2) % 3);

        const uint32_t ao = sb + s * STAGE;
        const uint32_t bho = ao + A_ST;
        const uint32_t blo = bho + B_ST;

#pragma unroll
        for (int ks = 0; ks < 2; ks++) {
            const int k0 = ks * 8;
            uint32_t ah[2][4];
#pragma unroll
            for (int f = 0; f < 2; f++) {
                int m = warpM * 32 + f * 16 + (ti & 1) * 8 + ri;
                uint32_t addr = ao + m * STRIDE_B + (k0 + (ti >> 1) * 4) * 4;
                ldsm_x4(ah[f][0], ah[f][1], ah[f][2], ah[f][3], addr);
#pragma unroll
                for (int q = 0; q < 4; q++)
                    ah[f][q] = f2tf32(__uint_as_float(ah[f][q]));
            }
            uint32_t bh[NFRAG][2], bl[NFRAG][2];
#pragma unroll
            for (int fp = 0; fp < NFRAG / 2; fp++) {
                int n = warpN * (NT / 2) + fp * 16 + (ti >> 1) * 8 + ri;
                uint32_t off = n * STRIDE_B + (k0 + (ti & 1) * 4) * 4;
                ldsm_x4(bh[2 * fp][0], bh[2 * fp][1], bh[2 * fp + 1][0],
                        bh[2 * fp + 1][1], bho + off);
                ldsm_x4(bl[2 * fp][0], bl[2 * fp][1], bl[2 * fp + 1][0],
                        bl[2 * fp + 1][1], blo + off);
            }
#pragma unroll
            for (int mf = 0; mf < 2; mf++)
#pragma unroll
                for (int nf = 0; nf < NFRAG; nf++) {
                    mma_tf32(acc[mf][nf], ah[mf], bl[nf]);
                    mma_tf32(acc[mf][nf], ah[mf], bh[nf]);
                }
        }
    }

#pragma unroll
    for (int mf = 0; mf < 2; mf++) {
        int row0 = brow + warpM * 32 + mf * 16 + (lane >> 2);
        int row1 = row0 + 8;
#pragma unroll
        for (int nf = 0; nf < NFRAG; nf++) {
            int col = warpN * (NT / 2) + nf * 8 + (lane & 3) * 2;
            if (HALF_OUT) {
                __half* C = (__half*)Cv;
                if (row0 < M)
                    *reinterpret_cast<__half2*>(C + (size_t)row0 * NT + col) =
                        __floats2half2_rn(acc[mf][nf][0], acc[mf][nf][1]);
                if (row1 < M)
                    *reinterpret_cast<__half2*>(C + (size_t)row1 * NT + col) =
                        __floats2half2_rn(acc[mf][nf][2], acc[mf][nf][3]);
            } else {
                float* C = (float*)Cv;
                if (row0 < M)
                    *reinterpret_cast<float2*>(C + (size_t)row0 * NT + col) =
                        make_float2(acc[mf][nf][0], acc[mf][nf][1]);
                if (row1 < M)
                    *reinterpret_cast<float2*>(C + (size_t)row1 * NT + col) =
                        make_float2(acc[mf][nf][2], acc[mf][nf][3]);
            }
        }
    }
}

// ---------------------------------------------------------------------------
// Weight transpose + hi/lo tf32 split
// ---------------------------------------------------------------------------
__global__ void k_transpose_split(const float* __restrict__ W,
                                  float* __restrict__ WTh,
                                  float* __restrict__ WTl, int K, int N) {
    int i = blockIdx.x * blockDim.x + threadIdx.x;
    if (i >= K * N) return;
    int k = i / N, nn = i % N;
    float w = W[i];
    uint32_t hb = f2tf32(w);
    float hi = __uint_as_float(hb);
    uint32_t lb = f2tf32(w - hi);
    WTh[(size_t)nn * K + k] = hi;
    WTl[(size_t)nn * K + k] = __uint_as_float(lb);
}

// ---------------------------------------------------------------------------
// CSR build (side stream)
// ---------------------------------------------------------------------------
__global__ void k_cnt(const int* __restrict__ dst, int* cnt, int e) {
    int i = blockIdx.x * blockDim.x + threadIdx.x;
    int base = i * 4;
    if (base + 3 < e) {
        int4 d = *reinterpret_cast<const int4*>(dst + base);
        atomicAdd(&cnt[d.x], 1);
        atomicAdd(&cnt[d.y], 1);
        atomicAdd(&cnt[d.z], 1);
        atomicAdd(&cnt[d.w], 1);
    } else {
        for (int j = base; j < e; j++) atomicAdd(&cnt[dst[j]], 1);
    }
}
__global__ void k_dinv(const int* __restrict__ cnt, float* dinv, int n) {
    int i = blockIdx.x * blockDim.x + threadIdx.x;
    if (i < n) dinv[i] = rsqrtf((float)(cnt[i] + 1));
}
__global__ void k_scan1(const int* __restrict__ cnt, int* scan, int* bsum, int n) {
    __shared__ int sh[SCAN_B];
    int i = blockIdx.x * SCAN_B + threadIdx.x;
    int v = (i < n) ? cnt[i] : 0;
    sh[threadIdx.x] = v;
    __syncthreads();
#pragma unroll
    for (int off = 1; off < SCAN_B; off <<= 1) {
        int t = (threadIdx.x >= off) ? sh[threadIdx.x - off] : 0;
        __syncthreads();
        sh[threadIdx.x] += t;
        __syncthreads();
    }
    if (i < n) scan[i] = sh[threadIdx.x];
    if (threadIdx.x == SCAN_B - 1) bsum[blockIdx.x] = sh[SCAN_B - 1];
}
__global__ void k_scan2(int* bsum, int nb) {
    __shared__ int sh[128];
    int v = (threadIdx.x < nb) ? bsum[threadIdx.x] : 0;
    sh[threadIdx.x] = v;
    __syncthreads();
#pragma unroll
    for (int off = 1; off < 128; off <<= 1) {
        int t = (threadIdx.x >= off) ? sh[threadIdx.x - off] : 0;
        __syncthreads();
        sh[threadIdx.x] += t;
        __syncthreads();
    }
    if (threadIdx.x < nb) bsum[threadIdx.x] = sh[threadIdx.x] - v;
}
__global__ void k_scan3(const int* __restrict__ cnt, const int* __restrict__ scan,
                        const int* __restrict__ bsum, int* rowptr, int* cursor, int n) {
    int i = blockIdx.x * blockDim.x + threadIdx.x;
    if (i >= n) return;
    int excl = scan[i] - cnt[i] + bsum[i / SCAN_B];
    rowptr[i] = excl;
    cursor[i] = excl;
    if (i == n - 1) rowptr[n] = excl + cnt[i];
}
__global__ void k_fill(const int* __restrict__ src, const int* __restrict__ dst,
                       const float* __restrict__ dinv, int* cursor,
                       int2* __restrict__ csr, int e) {
    int i = blockIdx.x * blockDim.x + threadIdx.x;
    int base = i * 4;
    if (base + 3 < e) {
        int4 sv = *reinterpret_cast<const int4*>(src + base);
        int4 dv = *reinterpret_cast<const int4*>(dst + base);
        const int ss[4] = {sv.x, sv.y, sv.z, sv.w};
        const int dd[4] = {dv.x, dv.y, dv.z, dv.w};
#pragma unroll
        for (int j = 0; j < 4; j++) {
            int pos = atomicAdd(&cursor[dd[j]], 1);
            csr[pos] = make_int2(ss[j],
                                 __float_as_int(dinv[ss[j]] * dinv[dd[j]]));
        }
    } else {
        for (int j = base; j < e; j++) {
            int s = src[j], d = dst[j];
            int pos = atomicAdd(&cursor[d], 1);
            csr[pos] = make_int2(s, __float_as_int(dinv[s] * dinv[d]));
        }
    }
}

// ---------------------------------------------------------------------------
// Warp-per-node aggregation (fp16 gathers).
// ---------------------------------------------------------------------------
__global__ void k_agg_csr128(const __half* __restrict__ h,
                             const int* __restrict__ rowptr,
                             const int2* __restrict__ csr,
                             const float* __restrict__ dinv,
                             const float* __restrict__ b1,
                             float* __restrict__ out, int n) {
    int node = (blockIdx.x * blockDim.x + threadIdx.x) >> 5;
    int lane = threadIdx.x & 31;
    if (node >= n) return;
    float di = dinv[node];
    float c = di * di;
    uint2 raw = *reinterpret_cast<const uint2*>(h + (size_t)node * 128 + lane * 4);
    float2 p0 = __half22float2(*reinterpret_cast<const __half2*>(&raw.x));
    float2 p1 = __half22float2(*reinterpret_cast<const __half2*>(&raw.y));
    float4 acc = make_float4(p0.x * c, p0.y * c, p1.x * c, p1.y * c);
    int idx = rowptr[node], end = rowptr[node + 1];
    for (; idx + 1 < end; idx += 2) {
        int2 e0 = csr[idx];
        int2 e1 = csr[idx + 1];
        float c0 = __int_as_float(e0.y);
        float c1 = __int_as_float(e1.y);
        uint2 r0 = *reinterpret_cast<const uint2*>(h + (size_t)e0.x * 128 + lane * 4);
        uint2 r1 = *reinterpret_cast<const uint2*>(h + (size_t)e1.x * 128 + lane * 4);
        float2 a0 = __half22float2(*reinterpret_cast<const __half2*>(&r0.x));
        float2 a1 = __half22float2(*reinterpret_cast<const __half2*>(&r0.y));
        float2 b0 = __half22float2(*reinterpret_cast<const __half2*>(&r1.x));
        float2 b1v = __half22float2(*reinterpret_cast<const __half2*>(&r1.y));
        acc.x = fmaf(a0.x, c0, acc.x); acc.y = fmaf(a0.y, c0, acc.y);
        acc.z = fmaf(a1.x, c0, acc.z); acc.w = fmaf(a1.y, c0, acc.w);
        acc.x = fmaf(b0.x, c1, acc.x); acc.y = fmaf(b0.y, c1, acc.y);
        acc.z = fmaf(b1v.x, c1, acc.z); acc.w = fmaf(b1v.y, c1, acc.w);
    }
    if (idx < end) {
        int2 e0 = csr[idx];
        float c0 = __int_as_float(e0.y);
        uint2 r0 = *reinterpret_cast<const uint2*>(h + (size_t)e0.x * 128 + lane * 4);
        float2 a0 = __half22float2(*reinterpret_cast<const __half2*>(&r0.x));
        float2 a1 = __half22float2(*reinterpret_cast<const __half2*>(&r0.y));
        acc.x = fmaf(a0.x, c0, acc.x); acc.y = fmaf(a0.y, c0, acc.y);
        acc.z = fmaf(a1.x, c0, acc.z); acc.w = fmaf(a1.y, c0, acc.w);
    }
    float4 b = *reinterpret_cast<const float4*>(b1 + lane * 4);
    acc.x = fmaxf(acc.x + b.x, 0.f);
    acc.y = fmaxf(acc.y + b.y, 0.f);
    acc.z = fmaxf(acc.z + b.z, 0.f);
    acc.w = fmaxf(acc.w + b.w, 0.f);
    *reinterpret_cast<float4*>(out + (size_t)node * 128 + lane * 4) = acc;
}

__global__ void k_agg_csr64(const __half* __restrict__ h,
                            const int* __restrict__ rowptr,
                            const int2* __restrict__ csr,
                            const float* __restrict__ dinv,
                            const float* __restrict__ bias,
                            float* __restrict__ out, int n) {
    int node = (blockIdx.x * blockDim.x + threadIdx.x) >> 5;
    int lane = threadIdx.x & 31;
    if (node >= n) return;
    float di = dinv[node];
    float c = di * di;
    uint32_t raw = *reinterpret_cast<const uint32_t*>(h + (size_t)node * 64 + lane * 2);
    float2 v = __half22float2(*reinterpret_cast<const __half2*>(&raw));
    float2 acc = make_float2(v.x * c, v.y * c);
    int idx = rowptr[node], end = rowptr[node + 1];
    for (; idx + 1 < end; idx += 2) {
        int2 e0 = csr[idx];
        int2 e1 = csr[idx + 1];
        float c0 = __int_as_float(e0.y);
        float c1 = __int_as_float(e1.y);
        uint32_t r0 = *reinterpret_cast<const uint32_t*>(h + (size_t)e0.x * 64 + lane * 2);
        uint32_t r1 = *reinterpret_cast<const uint32_t*>(h + (size_t)e1.x * 64 + lane * 2);
        float2 v0 = __half22float2(*reinterpret_cast<const __half2*>(&r0));
        float2 v1 = __half22float2(*reinterpret_cast<const __half2*>(&r1));
        acc.x = fmaf(v0.x, c0, acc.x); acc.y = fmaf(v0.y, c0, acc.y);
        acc.x = fmaf(v1.x, c1, acc.x); acc.y = fmaf(v1.y, c1, acc.y);
    }
    if (idx < end) {
        int2 e0 = csr[idx];
        float c0 = __int_as_float(e0.y);
        uint32_t r0 = *reinterpret_cast<const uint32_t*>(h + (size_t)e0.x * 64 + lane * 2);
        float2 v0 = __half22float2(*reinterpret_cast<const __half2*>(&r0));
        acc.x = fmaf(v0.x, c0, acc.x); acc.y = fmaf(v0.y, c0, acc.y);
    }
    float2 b = *reinterpret_cast<const float2*>(bias + lane * 2);
    acc.x += b.x;
    acc.y += b.y;
    *reinterpret_cast<float2*>(out + (size_t)node * 64 + lane * 2) = acc;
}

// ---------------------------------------------------------------------------
// Launch
// ---------------------------------------------------------------------------
extern "C" void kernel_launch(void* const* d_in, const int* in_sizes, int n_in,
                              void* d_out, int out_size) {
    const float* x = (const float*)d_in[0];
    const int* ei = (const int*)d_in[1];
    const float* W1 = (const float*)d_in[2];
    const float* b1 = (const float*)d_in[3];
    const float* W2 = (const float*)d_in[4];
    const float* b2 = (const float*)d_in[5];
    float* out = (float*)d_out;

    const int n = in_sizes[0] / IN_F;  // 100000
    const int e = in_sizes[1] / 2;     // 1600000
    const int* src = ei;
    const int* dst = ei + e;
    const int nb = (n + SCAN_B - 1) / SCAN_B;

    int *p_cnt, *p_scan, *p_bsum, *p_rowptr, *p_cursor;
    int2* p_csr;
    float *p_dinv, *p_agg1;
    __half *p_h1, *p_h2;
    float *p_w1h, *p_w1l, *p_w2h, *p_w2l;
    cudaGetSymbolAddress((void**)&p_cnt, g_cnt);
    cudaGetSymbolAddress((void**)&p_scan, g_scan);
    cudaGetSymbolAddress((void**)&p_bsum, g_bsum);
    cudaGetSymbolAddress((void**)&p_rowptr, g_rowptr);
    cudaGetSymbolAddress((void**)&p_cursor, g_cursor);
    cudaGetSymbolAddress((void**)&p_csr, g_csr);
    cudaGetSymbolAddress((void**)&p_dinv, g_dinv);
    cudaGetSymbolAddress((void**)&p_h1, g_h1);
    cudaGetSymbolAddress((void**)&p_agg1, g_agg1);
    cudaGetSymbolAddress((void**)&p_h2, g_h2);
    cudaGetSymbolAddress((void**)&p_w1h, g_w1t_hi);
    cudaGetSymbolAddress((void**)&p_w1l, g_w1t_lo);
    cudaGetSymbolAddress((void**)&p_w2h, g_w2t_hi);
    cudaGetSymbolAddress((void**)&p_w2l, g_w2t_lo);

    static cudaStream_t s2 = nullptr;
    static cudaEvent_t evFork = nullptr, evJoin = nullptr;
    if (s2 == nullptr) {
        cudaStreamCreateWithFlags(&s2, cudaStreamNonBlocking);
        cudaEventCreateWithFlags(&evFork, cudaEventDisableTiming);
        cudaEventCreateWithFlags(&evJoin, cudaEventDisableTiming);
    }

    // ---- fork: CSR build on side stream
    cudaEventRecord(evFork, 0);
    cudaStreamWaitEvent(s2, evFork, 0);
    cudaMemsetAsync(p_cnt, 0, (size_t)n * sizeof(int), s2);
    k_cnt<<<(e / 4 + 255) / 256, 256, 0, s2>>>(dst, p_cnt, e);
    k_dinv<<<(n + 255) / 256, 256, 0, s2>>>(p_cnt, p_dinv, n);
    k_scan1<<<nb, SCAN_B, 0, s2>>>(p_cnt, p_scan, p_bsum, n);
    k_scan2<<<1, 128, 0, s2>>>(p_bsum, nb);
    k_scan3<<<(n + 255) / 256, 256, 0, s2>>>(p_cnt, p_scan, p_bsum, p_rowptr,
                                             p_cursor, n);
    k_fill<<<(e / 4 + 255) / 256, 256, 0, s2>>>(src, dst, p_dinv, p_cursor,
                                                p_csr, e);
    cudaEventRecord(evJoin, s2);

    // ---- main stream: weight split-transposes + GEMM1 (fp16 out)
    k_transpose_split<<<(IN_F * HID + 255) / 256, 256>>>(W1, p_w1h, p_w1l, IN_F, HID);
    k_transpose_split<<<(HID * OUT_F + 255) / 256, 256>>>(W2, p_w2h, p_w2l, HID, OUT_F);

    const int grid_m = (n + 127) / 128;
    {
        constexpr int SMEM1 = 3 * (128 * 80 + 2 * HID * 80);  // 92160
        cudaFuncSetAttribute(k_mma_gemm<HID, IN_F, true>,
                             cudaFuncAttributeMaxDynamicSharedMemorySize, SMEM1);
        k_mma_gemm<HID, IN_F, true><<<grid_m, 256, SMEM1>>>(n, x, p_w1h, p_w1l,
                                                            p_h1);
    }

    // ---- join: aggregation needs the CSR
    cudaStreamWaitEvent(0, evJoin, 0);

    k_agg_csr128<<<(n * 32 + 255) / 256, 256>>>(p_h1, p_rowptr, p_csr, p_dinv,
                                                b1, p_agg1, n);

    {
        constexpr int SMEM2 = 3 * (128 * 80 + 2 * OUT_F * 80);  // 61440
        cudaFuncSetAttribute(k_mma_gemm<OUT_F, HID, true>,
                             cudaFuncAttributeMaxDynamicSharedMemorySize, SMEM2);
        k_mma_gemm<OUT_F, HID, true><<<grid_m, 256, SMEM2>>>(n, p_agg1, p_w2h,
                                                             p_w2l, p_h2);
    }

    k_agg_csr64<<<(n * 32 + 255) / 256, 256>>>(p_h2, p_rowptr, p_csr, p_dinv,
                                               b2, out, n);
}

// round 9
// speedup vs baseline: 4.6086x; 1.1647x over previous
#include <cuda_runtime.h>
#include <cuda_fp16.h>
#include <cuda_bf16.h>
#include <cstdint>

#define NMAX 100000
#define EMAX 1600000
#define IN_F 256
#define HID 128
#define OUT_F 64
#define SCAN_B 1024

// ---------------------------------------------------------------------------
// Scratch (bss, no runtime allocation)
// ---------------------------------------------------------------------------
__device__ int   g_cnt[NMAX];
__device__ int   g_scan[NMAX];
__device__ int   g_bsum[(NMAX + SCAN_B - 1) / SCAN_B];
__device__ int   g_rowptr[NMAX + 1];
__device__ int   g_cursor[NMAX];
__device__ __align__(16) int2  g_csr[EMAX];        // {src, coef-bits}
__device__ float g_dinv[NMAX];
__device__ __align__(128) __half g_h1[(size_t)NMAX * HID];    // fp16 h1
__device__ __align__(128) __half g_agg1[(size_t)NMAX * HID];  // fp16 relu(agg+b1)
__device__ __align__(128) __half g_h2[(size_t)NMAX * OUT_F];  // fp16 h2
__device__ __align__(128) __half g_w1t_hi[HID * IN_F];  // fp16 hi(W1^T)
__device__ __align__(128) __half g_w1t_lo[HID * IN_F];  // fp16 lo
__device__ __align__(128) __half g_w2t_hi[OUT_F * HID];
__device__ __align__(128) __half g_w2t_lo[OUT_F * HID];

// ---------------------------------------------------------------------------
// PTX helpers (baseline PTX only)
// ---------------------------------------------------------------------------
__device__ __forceinline__ uint32_t smem_u32(const void* p) {
    uint32_t a;
    asm("{ .reg .u64 t; cvta.to.shared.u64 t, %1; cvt.u32.u64 %0, t; }"
        : "=r"(a) : "l"(p));
    return a;
}
__device__ __forceinline__ void cp_async16(uint32_t sa, const void* g) {
    asm volatile("cp.async.cg.shared.global [%0], [%1], 16;" ::"r"(sa), "l"(g));
}
__device__ __forceinline__ void cp_commit() {
    asm volatile("cp.async.commit_group;");
}
template <int N>
__device__ __forceinline__ void cp_wait() {
    asm volatile("cp.async.wait_group %0;" ::"n"(N));
}
__device__ __forceinline__ void ldsm_x4(uint32_t& r0, uint32_t& r1, uint32_t& r2,
                                        uint32_t& r3, uint32_t addr) {
    asm volatile("ldmatrix.sync.aligned.m8n8.x4.shared.b16 {%0,%1,%2,%3}, [%4];"
                 : "=r"(r0), "=r"(r1), "=r"(r2), "=r"(r3) : "r"(addr));
}
__device__ __forceinline__ float2 lds64(uint32_t addr) {
    float2 v;
    asm volatile("ld.shared.v2.f32 {%0,%1}, [%2];"
                 : "=f"(v.x), "=f"(v.y) : "r"(addr));
    return v;
}
__device__ __forceinline__ uint32_t pack_h2(float lo, float hi) {
    __half2 h = __floats2half2_rn(lo, hi);
    return *reinterpret_cast<uint32_t*>(&h);
}
__device__ __forceinline__ void mma_f16(float* c, const uint32_t* a,
                                        const uint32_t* b) {
    asm volatile(
        "mma.sync.aligned.m16n8k16.row.col.f32.f16.f16.f32 "
        "{%0,%1,%2,%3}, {%4,%5,%6,%7}, {%8,%9}, {%0,%1,%2,%3};"
        : "+f"(c[0]), "+f"(c[1]), "+f"(c[2]), "+f"(c[3])
        : "r"(a[0]), "r"(a[1]), "r"(a[2]), "r"(a[3]), "r"(b[0]), "r"(b[1]));
}

// ---------------------------------------------------------------------------
// GEMM1: A fp32 in gmem/smem, converted to fp16 frags via LDS.64+cvt.
// B: pre-split fp16 hi/lo (2-term). D = A*Bh + A*Bl, fp32 accum, fp16 out.
// Block tile 128 x NT, BK = 16 (floats), 3-stage cp.async.
// ---------------------------------------------------------------------------
template <int NT, int KT>
__global__ void __launch_bounds__(256)
k_gemm_f32a(int M, const float* __restrict__ A, const __half* __restrict__ BTh,
            const __half* __restrict__ BTl, __half* __restrict__ C) {
    constexpr int BK = 16;               // floats per k-tile
    constexpr int T = KT / BK;
    constexpr int A_STR = 96;            // 64B data + 32B pad (conflict-free LDS)
    constexpr int B_STR = 48;            // 32B data + 16B pad
    constexpr int A_ST = 128 * A_STR;
    constexpr int B_ST = NT * B_STR;
    constexpr int STAGE = A_ST + 2 * B_ST;
    constexpr int NFRAG = NT / 16;       // n8 frags per warp

    extern __shared__ __align__(16) char smem[];
    const uint32_t sb = smem_u32(smem);
    const int tid = threadIdx.x;
    const int wid = tid >> 5, lane = tid & 31;
    const int warpM = wid >> 1, warpN = wid & 1;
    const int brow = blockIdx.x * 128;

    float acc[2][NFRAG][4];
#pragma unroll
    for (int i = 0; i < 2; i++)
#pragma unroll
        for (int j = 0; j < NFRAG; j++)
#pragma unroll
            for (int q = 0; q < 4; q++) acc[i][j][q] = 0.f;

    auto prefetch = [&](int t, int s) {
        const uint32_t ao = sb + s * STAGE;
        const uint32_t bho = ao + A_ST;
        const uint32_t blo = bho + B_ST;
#pragma unroll
        for (int i = tid; i < 128 * 4; i += 256) {   // A: 4 x 16B per row
            int m = i >> 2, q = i & 3;
            int gr = brow + m;
            if (gr >= M) gr = M - 1;
            cp_async16(ao + m * A_STR + q * 16,
                       A + (size_t)gr * KT + t * BK + q * 4);
        }
#pragma unroll
        for (int i = tid; i < NT * 2; i += 256) {    // B: 2 x 16B per row
            int r = i >> 1, q = i & 1;
            cp_async16(bho + r * B_STR + q * 16,
                       BTh + (size_t)r * KT + t * BK + q * 8);
            cp_async16(blo + r * B_STR + q * 16,
                       BTl + (size_t)r * KT + t * BK + q * 8);
        }
        cp_commit();
    };

    prefetch(0, 0);
    if (T > 1) prefetch(1, 1);

    const int ti = lane >> 3, ri = lane & 7;   // ldmatrix addressing
    const int r4 = lane >> 2, c4 = lane & 3;   // mma fragment owner coords

    for (int t = 0; t < T; t++) {
        const int s = t % 3;
        if (t + 1 < T) cp_wait<1>(); else cp_wait<0>();
        __syncthreads();
        if (t + 2 < T) prefetch(t + 2, (t + 2) % 3);

        const uint32_t ao = sb + s * STAGE;
        const uint32_t bho = ao + A_ST;
        const uint32_t blo = bho + B_ST;

        // --- A fragments: fp32 smem -> fp16 regs (thread owns k=2c,2c+1)
        uint32_t af[2][4];
#pragma unroll
        for (int mf = 0; mf < 2; mf++) {
            int m0 = warpM * 32 + mf * 16 + r4;
            uint32_t b0 = ao + m0 * A_STR + c4 * 8;
            uint32_t b1 = ao + (m0 + 8) * A_STR + c4 * 8;
            float2 f00 = lds64(b0);
            float2 f10 = lds64(b1);
            float2 f01 = lds64(b0 + 32);   // k+8
            float2 f11 = lds64(b1 + 32);
            af[mf][0] = pack_h2(f00.x, f00.y);
            af[mf][1] = pack_h2(f10.x, f10.y);
            af[mf][2] = pack_h2(f01.x, f01.y);
            af[mf][3] = pack_h2(f11.x, f11.y);
        }
        // --- B fragments (hi & lo)
        uint32_t bh[NFRAG][2], bl[NFRAG][2];
#pragma unroll
        for (int fp = 0; fp < NFRAG / 2; fp++) {
            int nr = warpN * (NT / 2) + fp * 16 + (ti >> 1) * 8 + ri;
            uint32_t off = nr * B_STR + (ti & 1) * 16;
            ldsm_x4(bh[2 * fp][0], bh[2 * fp][1], bh[2 * fp + 1][0],
                    bh[2 * fp + 1][1], bho + off);
            ldsm_x4(bl[2 * fp][0], bl[2 * fp][1], bl[2 * fp + 1][0],
                    bl[2 * fp + 1][1], blo + off);
        }
#pragma unroll
        for (int mf = 0; mf < 2; mf++)
#pragma unroll
            for (int nf = 0; nf < NFRAG; nf++) {
                mma_f16(acc[mf][nf], af[mf], bl[nf]);
                mma_f16(acc[mf][nf], af[mf], bh[nf]);
            }
    }

#pragma unroll
    for (int mf = 0; mf < 2; mf++) {
        int row0 = brow + warpM * 32 + mf * 16 + (lane >> 2);
        int row1 = row0 + 8;
#pragma unroll
        for (int nf = 0; nf < NFRAG; nf++) {
            int col = warpN * (NT / 2) + nf * 8 + (lane & 3) * 2;
            if (row0 < M)
                *reinterpret_cast<__half2*>(C + (size_t)row0 * NT + col) =
                    __floats2half2_rn(acc[mf][nf][0], acc[mf][nf][1]);
            if (row1 < M)
                *reinterpret_cast<__half2*>(C + (size_t)row1 * NT + col) =
                    __floats2half2_rn(acc[mf][nf][2], acc[mf][nf][3]);
        }
    }
}

// ---------------------------------------------------------------------------
// GEMM2: A fp16 (agg1), B pre-split fp16 hi/lo. Standard ldmatrix A path.
// ---------------------------------------------------------------------------
template <int NT, int KT>
__global__ void __launch_bounds__(256)
k_gemm_f16a(int M, const __half* __restrict__ A, const __half* __restrict__ BTh,
            const __half* __restrict__ BTl, __half* __restrict__ C) {
    constexpr int BK = 16;               // halves per k-tile
    constexpr int T = KT / BK;
    constexpr int STR = 48;              // 32B data + 16B pad
    constexpr int A_ST = 128 * STR;
    constexpr int B_ST = NT * STR;
    constexpr int STAGE = A_ST + 2 * B_ST;
    constexpr int NFRAG = NT / 16;

    extern __shared__ __align__(16) char smem[];
    const uint32_t sb = smem_u32(smem);
    const int tid = threadIdx.x;
    const int wid = tid >> 5, lane = tid & 31;
    const int warpM = wid >> 1, warpN = wid & 1;
    const int brow = blockIdx.x * 128;

    float acc[2][NFRAG][4];
#pragma unroll
    for (int i = 0; i < 2; i++)
#pragma unroll
        for (int j = 0; j < NFRAG; j++)
#pragma unroll
            for (int q = 0; q < 4; q++) acc[i][j][q] = 0.f;

    auto prefetch = [&](int t, int s) {
        const uint32_t ao = sb + s * STAGE;
        const uint32_t bho = ao + A_ST;
        const uint32_t blo = bho + B_ST;
#pragma unroll
        for (int i = tid; i < 128 * 2; i += 256) {
            int m = i >> 1, q = i & 1;
            int gr = brow + m;
            if (gr >= M) gr = M - 1;
            cp_async16(ao + m * STR + q * 16,
                       A + (size_t)gr * KT + t * BK + q * 8);
        }
#pragma unroll
        for (int i = tid; i < NT * 2; i += 256) {
            int r = i >> 1, q = i & 1;
            cp_async16(bho + r * STR + q * 16,
                       BTh + (size_t)r * KT + t * BK + q * 8);
            cp_async16(blo + r * STR + q * 16,
                       BTl + (size_t)r * KT + t * BK + q * 8);
        }
        cp_commit();
    };

    prefetch(0, 0);
    if (T > 1) prefetch(1, 1);

    const int ti = lane >> 3, ri = lane & 7;

    for (int t = 0; t < T; t++) {
        const int s = t % 3;
        if (t + 1 < T) cp_wait<1>(); else cp_wait<0>();
        __syncthreads();
        if (t + 2 < T) prefetch(t + 2, (t + 2) % 3);

        const uint32_t ao = sb + s * STAGE;
        const uint32_t bho = ao + A_ST;
        const uint32_t blo = bho + B_ST;

        uint32_t af[2][4];
#pragma unroll
        for (int mf = 0; mf < 2; mf++) {
            int m = warpM * 32 + mf * 16 + (ti & 1) * 8 + ri;
            uint32_t addr = ao + m * STR + (ti >> 1) * 16;
            ldsm_x4(af[mf][0], af[mf][1], af[mf][2], af[mf][3], addr);
        }
        uint32_t bh[NFRAG][2], bl[NFRAG][2];
#pragma unroll
        for (int fp = 0; fp < NFRAG / 2; fp++) {
            int nr = warpN * (NT / 2) + fp * 16 + (ti >> 1) * 8 + ri;
            uint32_t off = nr * STR + (ti & 1) * 16;
            ldsm_x4(bh[2 * fp][0], bh[2 * fp][1], bh[2 * fp + 1][0],
                    bh[2 * fp + 1][1], bho + off);
            ldsm_x4(bl[2 * fp][0], bl[2 * fp][1], bl[2 * fp + 1][0],
                    bl[2 * fp + 1][1], blo + off);
        }
#pragma unroll
        for (int mf = 0; mf < 2; mf++)
#pragma unroll
            for (int nf = 0; nf < NFRAG; nf++) {
                mma_f16(acc[mf][nf], af[mf], bl[nf]);
                mma_f16(acc[mf][nf], af[mf], bh[nf]);
            }
    }

#pragma unroll
    for (int mf = 0; mf < 2; mf++) {
        int row0 = brow + warpM * 32 + mf * 16 + (lane >> 2);
        int row1 = row0 + 8;
#pragma unroll
        for (int nf = 0; nf < NFRAG; nf++) {
            int col = warpN * (NT / 2) + nf * 8 + (lane & 3) * 2;
            if (row0 < M)
                *reinterpret_cast<__half2*>(C + (size_t)row0 * NT + col) =
                    __floats2half2_rn(acc[mf][nf][0], acc[mf][nf][1]);
            if (row1 < M)
                *reinterpret_cast<__half2*>(C + (size_t)row1 * NT + col) =
                    __floats2half2_rn(acc[mf][nf][2], acc[mf][nf][3]);
        }
    }
}

// ---------------------------------------------------------------------------
// Weight transpose + hi/lo fp16 split
// ---------------------------------------------------------------------------
__global__ void k_transpose_split(const float* __restrict__ W,
                                  __half* __restrict__ WTh,
                                  __half* __restrict__ WTl, int K, int N) {
    int i = blockIdx.x * blockDim.x + threadIdx.x;
    if (i >= K * N) return;
    int k = i / N, nn = i % N;
    float w = W[i];
    __half hi = __float2half_rn(w);
    __half lo = __float2half_rn(w - __half2float(hi));
    WTh[(size_t)nn * K + k] = hi;
    WTl[(size_t)nn * K + k] = lo;
}

// ---------------------------------------------------------------------------
// CSR build (side stream)
// ---------------------------------------------------------------------------
__global__ void k_cnt(const int* __restrict__ dst, int* cnt, int e) {
    int i = blockIdx.x * blockDim.x + threadIdx.x;
    int base = i * 4;
    if (base + 3 < e) {
        int4 d = *reinterpret_cast<const int4*>(dst + base);
        atomicAdd(&cnt[d.x], 1);
        atomicAdd(&cnt[d.y], 1);
        atomicAdd(&cnt[d.z], 1);
        atomicAdd(&cnt[d.w], 1);
    } else {
        for (int j = base; j < e; j++) atomicAdd(&cnt[dst[j]], 1);
    }
}
__global__ void k_dinv(const int* __restrict__ cnt, float* dinv, int n) {
    int i = blockIdx.x * blockDim.x + threadIdx.x;
    if (i < n) dinv[i] = rsqrtf((float)(cnt[i] + 1));
}
__global__ void k_scan1(const int* __restrict__ cnt, int* scan, int* bsum, int n) {
    __shared__ int sh[SCAN_B];
    int i = blockIdx.x * SCAN_B + threadIdx.x;
    int v = (i < n) ? cnt[i] : 0;
    sh[threadIdx.x] = v;
    __syncthreads();
#pragma unroll
    for (int off = 1; off < SCAN_B; off <<= 1) {
        int t = (threadIdx.x >= off) ? sh[threadIdx.x - off] : 0;
        __syncthreads();
        sh[threadIdx.x] += t;
        __syncthreads();
    }
    if (i < n) scan[i] = sh[threadIdx.x];
    if (threadIdx.x == SCAN_B - 1) bsum[blockIdx.x] = sh[SCAN_B - 1];
}
__global__ void k_scan2(int* bsum, int nb) {
    __shared__ int sh[128];
    int v = (threadIdx.x < nb) ? bsum[threadIdx.x] : 0;
    sh[threadIdx.x] = v;
    __syncthreads();
#pragma unroll
    for (int off = 1; off < 128; off <<= 1) {
        int t = (threadIdx.x >= off) ? sh[threadIdx.x - off] : 0;
        __syncthreads();
        sh[threadIdx.x] += t;
        __syncthreads();
    }
    if (threadIdx.x < nb) bsum[threadIdx.x] = sh[threadIdx.x] - v;
}
__global__ void k_scan3(const int* __restrict__ cnt, const int* __restrict__ scan,
                        const int* __restrict__ bsum, int* rowptr, int* cursor, int n) {
    int i = blockIdx.x * blockDim.x + threadIdx.x;
    if (i >= n) return;
    int excl = scan[i] - cnt[i] + bsum[i / SCAN_B];
    rowptr[i] = excl;
    cursor[i] = excl;
    if (i == n - 1) rowptr[n] = excl + cnt[i];
}
__global__ void k_fill(const int* __restrict__ src, const int* __restrict__ dst,
                       const float* __restrict__ dinv, int* cursor,
                       int2* __restrict__ csr, int e) {
    int i = blockIdx.x * blockDim.x + threadIdx.x;
    int base = i * 4;
    if (base + 3 < e) {
        int4 sv = *reinterpret_cast<const int4*>(src + base);
        int4 dv = *reinterpret_cast<const int4*>(dst + base);
        const int ss[4] = {sv.x, sv.y, sv.z, sv.w};
        const int dd[4] = {dv.x, dv.y, dv.z, dv.w};
#pragma unroll
        for (int j = 0; j < 4; j++) {
            int pos = atomicAdd(&cursor[dd[j]], 1);
            csr[pos] = make_int2(ss[j],
                                 __float_as_int(dinv[ss[j]] * dinv[dd[j]]));
        }
    } else {
        for (int j = base; j < e; j++) {
            int s = src[j], d = dst[j];
            int pos = atomicAdd(&cursor[d], 1);
            csr[pos] = make_int2(s, __float_as_int(dinv[s] * dinv[d]));
        }
    }
}

// ---------------------------------------------------------------------------
// Warp-per-node aggregation (fp16 gathers).
// agg1: +b1, relu, fp16 out (feeds fp16 GEMM2 directly).
// ---------------------------------------------------------------------------
__global__ void k_agg_csr128(const __half* __restrict__ h,
                             const int* __restrict__ rowptr,
                             const int2* __restrict__ csr,
                             const float* __restrict__ dinv,
                             const float* __restrict__ b1,
                             __half* __restrict__ out, int n) {
    int node = (blockIdx.x * blockDim.x + threadIdx.x) >> 5;
    int lane = threadIdx.x & 31;
    if (node >= n) return;
    float di = dinv[node];
    float c = di * di;
    uint2 raw = *reinterpret_cast<const uint2*>(h + (size_t)node * 128 + lane * 4);
    float2 p0 = __half22float2(*reinterpret_cast<const __half2*>(&raw.x));
    float2 p1 = __half22float2(*reinterpret_cast<const __half2*>(&raw.y));
    float4 acc = make_float4(p0.x * c, p0.y * c, p1.x * c, p1.y * c);
    int idx = rowptr[node], end = rowptr[node + 1];
    for (; idx + 1 < end; idx += 2) {
        int2 e0 = csr[idx];
        int2 e1 = csr[idx + 1];
        float c0 = __int_as_float(e0.y);
        float c1 = __int_as_float(e1.y);
        uint2 r0 = *reinterpret_cast<const uint2*>(h + (size_t)e0.x * 128 + lane * 4);
        uint2 r1 = *reinterpret_cast<const uint2*>(h + (size_t)e1.x * 128 + lane * 4);
        float2 a0 = __half22float2(*reinterpret_cast<const __half2*>(&r0.x));
        float2 a1 = __half22float2(*reinterpret_cast<const __half2*>(&r0.y));
        float2 b0 = __half22float2(*reinterpret_cast<const __half2*>(&r1.x));
        float2 b1v = __half22float2(*reinterpret_cast<const __half2*>(&r1.y));
        acc.x = fmaf(a0.x, c0, acc.x); acc.y = fmaf(a0.y, c0, acc.y);
        acc.z = fmaf(a1.x, c0, acc.z); acc.w = fmaf(a1.y, c0, acc.w);
        acc.x = fmaf(b0.x, c1, acc.x); acc.y = fmaf(b0.y, c1, acc.y);
        acc.z = fmaf(b1v.x, c1, acc.z); acc.w = fmaf(b1v.y, c1, acc.w);
    }
    if (idx < end) {
        int2 e0 = csr[idx];
        float c0 = __int_as_float(e0.y);
        uint2 r0 = *reinterpret_cast<const uint2*>(h + (size_t)e0.x * 128 + lane * 4);
        float2 a0 = __half22float2(*reinterpret_cast<const __half2*>(&r0.x));
        float2 a1 = __half22float2(*reinterpret_cast<const __half2*>(&r0.y));
        acc.x = fmaf(a0.x, c0, acc.x); acc.y = fmaf(a0.y, c0, acc.y);
        acc.z = fmaf(a1.x, c0, acc.z); acc.w = fmaf(a1.y, c0, acc.w);
    }
    float4 b = *reinterpret_cast<const float4*>(b1 + lane * 4);
    __half2 o0 = __floats2half2_rn(fmaxf(acc.x + b.x, 0.f), fmaxf(acc.y + b.y, 0.f));
    __half2 o1 = __floats2half2_rn(fmaxf(acc.z + b.z, 0.f), fmaxf(acc.w + b.w, 0.f));
    uint2 o;
    o.x = *reinterpret_cast<uint32_t*>(&o0);
    o.y = *reinterpret_cast<uint32_t*>(&o1);
    *reinterpret_cast<uint2*>(out + (size_t)node * 128 + lane * 4) = o;
}

__global__ void k_agg_csr64(const __half* __restrict__ h,
                            const int* __restrict__ rowptr,
                            const int2* __restrict__ csr,
                            const float* __restrict__ dinv,
                            const float* __restrict__ bias,
                            float* __restrict__ out, int n) {
    int node = (blockIdx.x * blockDim.x + threadIdx.x) >> 5;
    int lane = threadIdx.x & 31;
    if (node >= n) return;
    float di = dinv[node];
    float c = di * di;
    uint32_t raw = *reinterpret_cast<const uint32_t*>(h + (size_t)node * 64 + lane * 2);
    float2 v = __half22float2(*reinterpret_cast<const __half2*>(&raw));
    float2 acc = make_float2(v.x * c, v.y * c);
    int idx = rowptr[node], end = rowptr[node + 1];
    for (; idx + 1 < end; idx += 2) {
        int2 e0 = csr[idx];
        int2 e1 = csr[idx + 1];
        float c0 = __int_as_float(e0.y);
        float c1 = __int_as_float(e1.y);
        uint32_t r0 = *reinterpret_cast<const uint32_t*>(h + (size_t)e0.x * 64 + lane * 2);
        uint32_t r1 = *reinterpret_cast<const uint32_t*>(h + (size_t)e1.x * 64 + lane * 2);
        float2 v0 = __half22float2(*reinterpret_cast<const __half2*>(&r0));
        float2 v1 = __half22float2(*reinterpret_cast<const __half2*>(&r1));
        acc.x = fmaf(v0.x, c0, acc.x); acc.y = fmaf(v0.y, c0, acc.y);
        acc.x = fmaf(v1.x, c1, acc.x); acc.y = fmaf(v1.y, c1, acc.y);
    }
    if (idx < end) {
        int2 e0 = csr[idx];
        float c0 = __int_as_float(e0.y);
        uint32_t r0 = *reinterpret_cast<const uint32_t*>(h + (size_t)e0.x * 64 + lane * 2);
        float2 v0 = __half22float2(*reinterpret_cast<const __half2*>(&r0));
        acc.x = fmaf(v0.x, c0, acc.x); acc.y = fmaf(v0.y, c0, acc.y);
    }
    float2 b = *reinterpret_cast<const float2*>(bias + lane * 2);
    acc.x += b.x;
    acc.y += b.y;
    *reinterpret_cast<float2*>(out + (size_t)node * 64 + lane * 2) = acc;
}

// ---------------------------------------------------------------------------
// Launch
// ---------------------------------------------------------------------------
extern "C" void kernel_launch(void* const* d_in, const int* in_sizes, int n_in,
                              void* d_out, int out_size) {
    const float* x = (const float*)d_in[0];
    const int* ei = (const int*)d_in[1];
    const float* W1 = (const float*)d_in[2];
    const float* b1 = (const float*)d_in[3];
    const float* W2 = (const float*)d_in[4];
    const float* b2 = (const float*)d_in[5];
    float* out = (float*)d_out;

    const int n = in_sizes[0] / IN_F;  // 100000
    const int e = in_sizes[1] / 2;     // 1600000
    const int* src = ei;
    const int* dst = ei + e;
    const int nb = (n + SCAN_B - 1) / SCAN_B;

    int *p_cnt, *p_scan, *p_bsum, *p_rowptr, *p_cursor;
    int2* p_csr;
    float* p_dinv;
    __half *p_h1, *p_agg1, *p_h2;
    __half *p_w1h, *p_w1l, *p_w2h, *p_w2l;
    cudaGetSymbolAddress((void**)&p_cnt, g_cnt);
    cudaGetSymbolAddress((void**)&p_scan, g_scan);
    cudaGetSymbolAddress((void**)&p_bsum, g_bsum);
    cudaGetSymbolAddress((void**)&p_rowptr, g_rowptr);
    cudaGetSymbolAddress((void**)&p_cursor, g_cursor);
    cudaGetSymbolAddress((void**)&p_csr, g_csr);
    cudaGetSymbolAddress((void**)&p_dinv, g_dinv);
    cudaGetSymbolAddress((void**)&p_h1, g_h1);
    cudaGetSymbolAddress((void**)&p_agg1, g_agg1);
    cudaGetSymbolAddress((void**)&p_h2, g_h2);
    cudaGetSymbolAddress((void**)&p_w1h, g_w1t_hi);
    cudaGetSymbolAddress((void**)&p_w1l, g_w1t_lo);
    cudaGetSymbolAddress((void**)&p_w2h, g_w2t_hi);
    cudaGetSymbolAddress((void**)&p_w2l, g_w2t_lo);

    static cudaStream_t s2 = nullptr;
    static cudaEvent_t evFork = nullptr, evJoin = nullptr;
    if (s2 == nullptr) {
        cudaStreamCreateWithFlags(&s2, cudaStreamNonBlocking);
        cudaEventCreateWithFlags(&evFork, cudaEventDisableTiming);
        cudaEventCreateWithFlags(&evJoin, cudaEventDisableTiming);
    }

    // ---- fork: CSR build on side stream
    cudaEventRecord(evFork, 0);
    cudaStreamWaitEvent(s2, evFork, 0);
    cudaMemsetAsync(p_cnt, 0, (size_t)n * sizeof(int), s2);
    k_cnt<<<(e / 4 + 255) / 256, 256, 0, s2>>>(dst, p_cnt, e);
    k_dinv<<<(n + 255) / 256, 256, 0, s2>>>(p_cnt, p_dinv, n);
    k_scan1<<<nb, SCAN_B, 0, s2>>>(p_cnt, p_scan, p_bsum, n);
    k_scan2<<<1, 128, 0, s2>>>(p_bsum, nb);
    k_scan3<<<(n + 255) / 256, 256, 0, s2>>>(p_cnt, p_scan, p_bsum, p_rowptr,
                                             p_cursor, n);
    k_fill<<<(e / 4 + 255) / 256, 256, 0, s2>>>(src, dst, p_dinv, p_cursor,
                                                p_csr, e);
    cudaEventRecord(evJoin, s2);

    // ---- main stream: weight split-transposes + GEMM1
    k_transpose_split<<<(IN_F * HID + 255) / 256, 256>>>(W1, p_w1h, p_w1l, IN_F, HID);
    k_transpose_split<<<(HID * OUT_F + 255) / 256, 256>>>(W2, p_w2h, p_w2l, HID, OUT_F);

    const int grid_m = (n + 127) / 128;
    {
        constexpr int SMEM1 = 3 * (128 * 96 + 2 * HID * 48);  // 73728
        cudaFuncSetAttribute(k_gemm_f32a<HID, IN_F>,
                             cudaFuncAttributeMaxDynamicSharedMemorySize, SMEM1);
        k_gemm_f32a<HID, IN_F><<<grid_m, 256, SMEM1>>>(n, x, p_w1h, p_w1l, p_h1);
    }

    // ---- join: aggregation needs the CSR
    cudaStreamWaitEvent(0, evJoin, 0);

    k_agg_csr128<<<(n * 32 + 255) / 256, 256>>>(p_h1, p_rowptr, p_csr, p_dinv,
                                                b1, p_agg1, n);

    {
        constexpr int SMEM2 = 3 * (128 * 48 + 2 * OUT_F * 48);  // 36864
        cudaFuncSetAttribute(k_gemm_f16a<OUT_F, HID>,
                             cudaFuncAttributeMaxDynamicSharedMemorySize, SMEM2);
        k_gemm_f16a<OUT_F, HID><<<grid_m, 256, SMEM2>>>(n, p_agg1, p_w2h, p_w2l,
                                                        p_h2);
    }

    k_agg_csr64<<<(n * 32 + 255) / 256, 256>>>(p_h2, p_rowptr, p_csr, p_dinv,
                                               b2, out, n);
}